// round 13
// baseline (speedup 1.0000x reference)
#include <cuda_runtime.h>
#include <cuda_bf16.h>
#include <math.h>
#include <stdint.h>

#define Bc 256
#define Qc 512
#define Dc 32
#define Hc 192
#define HIDc 384
#define INCHc 96
#define KERc 9
#define WOUTc 64
#define PI_F 3.14159265358979f

// ---------------- scratch (all fp32 — trunk precision is load-bearing) ----------------
__device__ __align__(16) float g_h   [(size_t)Bc*Qc*Hc];    // residual (B,Q,H)
__device__ __align__(16) float g_af  [(size_t)Bc*Qc*Hc];    // LN'd act (B,Q,H)
__device__ __align__(16) float g_midf[(size_t)Bc*Qc*HIDc];  // pw1 out  (B,Q,HID)
__device__ __align__(16) float g_hseq[(size_t)Bc*Qc*Hc];    // only t=511 rows used
__device__ float g_gxsq[Bc*HIDc];
__device__ float g_scale[Bc*HIDc];
__device__ float g_rpg [(size_t)Bc*Qc*34];
__device__ float g_xpost[Bc*Dc];
__device__ float g_hr  [Bc*Hc];
__device__ float g_xr  [Bc*Hc];
__device__ float g_gi  [Bc*3*Hc];
__device__ float g_gh  [Bc*3*Hc];
__device__ float g_curr[Bc*Dc];
__device__ unsigned g_cnt;
__device__ volatile unsigned g_gen;

// ---------------- helpers ----------------
__device__ __forceinline__ float sigm(float x){ return 1.f/(1.f+expf(-x)); }
__device__ __forceinline__ float gelu_exact(float x){ return 0.5f*x*(1.f+erff(x*0.70710678118654752f)); }
__device__ __forceinline__ float wred(float v){
#pragma unroll
  for(int s=16;s;s>>=1) v += __shfl_xor_sync(0xffffffffu, v, s);
  return v;
}
__device__ __forceinline__ void ffma2(unsigned long long &acc, unsigned long long a, unsigned long long b){
  asm("fma.rn.f32x2 %0, %1, %2, %0;" : "+l"(acc) : "l"(a), "l"(b));
}
__device__ __forceinline__ float2 unpk(unsigned long long p){
  float2 f; asm("mov.b64 {%0, %1}, %2;" : "=f"(f.x), "=f"(f.y) : "l"(p));
  return f;
}

// ============ 1) features + input projection -> g_h (B,Q,H) ============
__global__ void __launch_bounds__(256) k_featproj(const float* __restrict__ x,
                                                  const float* __restrict__ W,
                                                  const float* __restrict__ bias){
  int t0 = blockIdx.x*64, o0 = blockIdx.y*64, b = blockIdx.z;
  __shared__ __align__(16) float Xs[66][33];
  __shared__ __align__(16) float As[32][64];
  __shared__ __align__(16) float Ws[32][68];
  int tid = threadIdx.x;
  for(int e=tid; e<66*32; e+=256){
    int i = e>>5, d = e&31;
    int tg = t0 - 2 + i;
    float v = 0.f;
    if(tg>=0 && tg<Qc) v = x[((size_t)b*Qc + tg)*Dc + d];
    Xs[i][d] = v;
  }
  int tx = tid & 15, ty = tid >> 4;
  float acc[4][4] = {};
  for(int j=0;j<3;j++){
    __syncthreads();
    for(int e=tid; e<2048; e+=256){
      int k = e>>6, t = e&63;
      int tg = t0+t;
      float x0 = Xs[t+2][k], x1 = Xs[t+1][k], x2 = Xs[t][k];
      float v;
      if(j==0)      v = x0;
      else if(j==1) v = (tg>=1)? x0-x1 : 0.f;
      else          v = (tg>=2)? (x0-2.f*x1+x2) : ((tg==1)? x0-x1 : 0.f);
      As[k][t] = v;
    }
    for(int e=tid; e<2048; e+=256){
      int o = e>>5, k = e&31;
      Ws[k][o] = W[(size_t)(o0+o)*INCHc + j*32 + k];
    }
    __syncthreads();
#pragma unroll
    for(int k=0;k<32;k++){
      float4 a = *(const float4*)&As[k][tx<<2];
      float4 w = *(const float4*)&Ws[k][ty<<2];
      acc[0][0]+=w.x*a.x; acc[0][1]+=w.x*a.y; acc[0][2]+=w.x*a.z; acc[0][3]+=w.x*a.w;
      acc[1][0]+=w.y*a.x; acc[1][1]+=w.y*a.y; acc[1][2]+=w.y*a.z; acc[1][3]+=w.y*a.w;
      acc[2][0]+=w.z*a.x; acc[2][1]+=w.z*a.y; acc[2][2]+=w.z*a.z; acc[2][3]+=w.z*a.w;
      acc[3][0]+=w.w*a.x; acc[3][1]+=w.w*a.y; acc[3][2]+=w.w*a.z; acc[3][3]+=w.w*a.w;
    }
  }
  float4 bo = *(const float4*)&bias[o0 + (ty<<2)];
#pragma unroll
  for(int jj=0;jj<4;jj++){
    int t = t0 + (tx<<2) + jj;
    float4 v;
    v.x = acc[0][jj] + bo.x;
    v.y = acc[1][jj] + bo.y;
    v.z = acc[2][jj] + bo.z;
    v.w = acc[3][jj] + bo.w;
    *(float4*)&g_h[((size_t)b*Qc + t)*Hc + o0 + (ty<<2)] = v;
  }
}

// ============ 2) dwconv (k=9 edge pad) + LN -> g_af fp32 (B,Q,H); zero gxsq ============
__global__ void __launch_bounds__(256) k_dwconv_ln(const float* __restrict__ dww,
                                                   const float* __restrict__ dwb,
                                                   const float* __restrict__ lnw,
                                                   const float* __restrict__ lnb){
  int t0 = blockIdx.x*16, b = blockIdx.y;
  __shared__ __align__(16) float In[24][Hc];
  __shared__ __align__(16) float Outp[16][Hc];
  __shared__ float Wd[Hc*KERc];
  __shared__ float Bd[Hc], Lw[Hc], Lb[Hc];
  int tid = threadIdx.x;
  if(blockIdx.x==0){
    for(int e=tid; e<HIDc; e+=256) g_gxsq[b*HIDc+e] = 0.f;
  }
  for(int e=tid; e<24*48; e+=256){
    int i = e/48, q = e%48;
    int tg = t0 - 4 + i;
    tg = tg < 0 ? 0 : (tg > Qc-1 ? Qc-1 : tg);
    *(float4*)&In[i][q*4] = *(const float4*)&g_h[((size_t)b*Qc + tg)*Hc + q*4];
  }
  for(int e=tid; e<Hc*KERc; e+=256) Wd[e] = dww[e];
  for(int e=tid; e<Hc; e+=256){ Bd[e] = dwb[e]; Lw[e] = lnw[e]; Lb[e] = lnb[e]; }
  __syncthreads();
  for(int e=tid; e<16*Hc; e+=256){
    int t = e/Hc, c = e%Hc;
    float acc = Bd[c];
#pragma unroll
    for(int k=0;k<KERc;k++) acc += In[t+k][c]*Wd[c*KERc+k];
    Outp[t][c] = acc;
  }
  __syncthreads();
  int w = tid>>5, lane = tid&31;
  for(int rep=0; rep<2; rep++){
    int t = w + rep*8;
    float v[6]; float s = 0.f;
#pragma unroll
    for(int j=0;j<6;j++){ v[j] = Outp[t][lane+32*j]; s += v[j]; }
    s = wred(s);
    float m = s*(1.f/192.f);
    float sq = 0.f;
#pragma unroll
    for(int j=0;j<6;j++){ float d = v[j]-m; sq += d*d; }
    sq = wred(sq);
    float rstd = rsqrtf(sq*(1.f/192.f) + 1e-5f);
#pragma unroll
    for(int j=0;j<6;j++){
      int c = lane+32*j;
      Outp[t][c] = (v[j]-m)*rstd*Lw[c] + Lb[c];
    }
  }
  __syncthreads();
  for(int e=tid; e<16*48; e+=256){
    int t = e/48, q = e%48;
    *(float4*)&g_af[((size_t)b*Qc + t0 + t)*Hc + q*4] = *(float4*)&Outp[t][q*4];
  }
}

// ============ 3) pw1: f32x2 GEMM (M=128 t, N=64 o, K=192); A pre-duplicated in smem ============
#define A2S 262
__global__ void __launch_bounds__(128,4) k_pw1x(const float* __restrict__ W,
                                                const float* __restrict__ bias){
  __shared__ __align__(16) float As2[32][A2S];
  __shared__ __align__(16) float Ws[32][68];
  __shared__ float osq[64];
  int t0 = blockIdx.x*128, o0 = blockIdx.y*64, b = blockIdx.z;
  int tid = threadIdx.x, tx = tid&15, ty = tid>>4;  // ty 0..7
  if(tid<64) osq[tid] = 0.f;
  unsigned long long acc[4][8] = {};
  const float* Ag = g_af + ((size_t)b*Qc + t0)*Hc;
  for(int c0=0;c0<Hc;c0+=32){
    __syncthreads();
    for(int e=tid;e<1024;e+=128){
      int kq=e&7, t=e>>3;
      float4 v = *(const float4*)&Ag[(size_t)t*Hc + c0 + kq*4];
      *(float2*)&As2[kq*4+0][2*t] = make_float2(v.x, v.x);
      *(float2*)&As2[kq*4+1][2*t] = make_float2(v.y, v.y);
      *(float2*)&As2[kq*4+2][2*t] = make_float2(v.z, v.z);
      *(float2*)&As2[kq*4+3][2*t] = make_float2(v.w, v.w);
    }
    for(int e=tid;e<512;e+=128){
      int o=e>>3, kq=e&7;
      float4 w = *(const float4*)&W[(size_t)(o0+o)*Hc + c0 + kq*4];
      Ws[kq*4+0][o]=w.x; Ws[kq*4+1][o]=w.y; Ws[kq*4+2][o]=w.z; Ws[kq*4+3][o]=w.w;
    }
    __syncthreads();
#pragma unroll 8
    for(int k=0;k<32;k++){
      ulonglong2 wv = *(const ulonglong2*)&Ws[k][tx*4];
#pragma unroll
      for(int j=0;j<8;j++){
        unsigned long long ad0 = *(const unsigned long long*)&As2[k][2*(ty*8+j)];
        unsigned long long ad1 = *(const unsigned long long*)&As2[k][128 + 2*(ty*8+j)];
        ffma2(acc[0][j], wv.x, ad0);
        ffma2(acc[1][j], wv.y, ad0);
        ffma2(acc[2][j], wv.x, ad1);
        ffma2(acc[3][j], wv.y, ad1);
      }
    }
  }
  float4 bo = *(const float4*)&bias[o0 + tx*4];
  float sq[4] = {};
#pragma unroll
  for(int g=0;g<2;g++){
#pragma unroll
    for(int j=0;j<8;j++){
      int t = t0 + g*64 + ty*8 + j;
      float2 p0 = unpk(acc[2*g][j]);
      float2 p1 = unpk(acc[2*g+1][j]);
      float4 v;
      v.x = gelu_exact(p0.x + bo.x);
      v.y = gelu_exact(p0.y + bo.y);
      v.z = gelu_exact(p1.x + bo.z);
      v.w = gelu_exact(p1.y + bo.w);
      sq[0]+=v.x*v.x; sq[1]+=v.y*v.y; sq[2]+=v.z*v.z; sq[3]+=v.w*v.w;
      *(float4*)&g_midf[((size_t)b*Qc + t)*HIDc + o0 + tx*4] = v;
    }
  }
  atomicAdd(&osq[tx*4+0], sq[0]);
  atomicAdd(&osq[tx*4+1], sq[1]);
  atomicAdd(&osq[tx*4+2], sq[2]);
  atomicAdd(&osq[tx*4+3], sq[3]);
  __syncthreads();
  if(tid<64) atomicAdd(&g_gxsq[b*HIDc + o0 + tid], osq[tid]);
}

// ============ 4) GRN scale ============
__global__ void k_grn_scale(const float* __restrict__ gg){
  int b = blockIdx.x, o = threadIdx.x;
  int w = o>>5, lane = o&31;
  float v = sqrtf(g_gxsq[b*HIDc + o]);
  float s = wred(v);
  __shared__ float red[12];
  if(lane==0) red[w] = s;
  __syncthreads();
  float tot = 0.f;
#pragma unroll
  for(int i=0;i<12;i++) tot += red[i];
  float mean = tot*(1.f/384.f);
  g_scale[b*HIDc + o] = 1.f + gg[o]*v/(mean + 1e-6f);
}

// ============ 5) pw2: f32x2 GEMM (M=128 t, N=64 o, K=384) on GRN-transformed y + residual ============
__global__ void __launch_bounds__(128,4) k_pw2x(const float* __restrict__ W,
                                                const float* __restrict__ bias,
                                                const float* __restrict__ grnb){
  __shared__ __align__(16) float As2[32][A2S];
  __shared__ __align__(16) float Ws[32][68];
  __shared__ float sc_s[HIDc], gb_s[HIDc];
  int t0 = blockIdx.x*128, o0 = blockIdx.y*64, b = blockIdx.z;
  int tid = threadIdx.x, tx = tid&15, ty = tid>>4;
  for(int e=tid; e<HIDc; e+=128){ sc_s[e] = g_scale[b*HIDc+e]; gb_s[e] = grnb[e]; }
  unsigned long long acc[4][8] = {};
  const float* Ag = g_midf + ((size_t)b*Qc + t0)*HIDc;
  for(int c0=0;c0<HIDc;c0+=32){
    __syncthreads();
    for(int e=tid;e<1024;e+=128){
      int kq=e&7, t=e>>3;
      int c = c0 + kq*4;
      float4 m = *(const float4*)&Ag[(size_t)t*HIDc + c];
      float a0 = m.x*sc_s[c+0] + gb_s[c+0];
      float a1 = m.y*sc_s[c+1] + gb_s[c+1];
      float a2 = m.z*sc_s[c+2] + gb_s[c+2];
      float a3 = m.w*sc_s[c+3] + gb_s[c+3];
      *(float2*)&As2[kq*4+0][2*t] = make_float2(a0, a0);
      *(float2*)&As2[kq*4+1][2*t] = make_float2(a1, a1);
      *(float2*)&As2[kq*4+2][2*t] = make_float2(a2, a2);
      *(float2*)&As2[kq*4+3][2*t] = make_float2(a3, a3);
    }
    for(int e=tid;e<512;e+=128){
      int o=e>>3, kq=e&7;
      float4 w = *(const float4*)&W[(size_t)(o0+o)*HIDc + c0 + kq*4];
      Ws[kq*4+0][o]=w.x; Ws[kq*4+1][o]=w.y; Ws[kq*4+2][o]=w.z; Ws[kq*4+3][o]=w.w;
    }
    __syncthreads();
#pragma unroll 8
    for(int k=0;k<32;k++){
      ulonglong2 wv = *(const ulonglong2*)&Ws[k][tx*4];
#pragma unroll
      for(int j=0;j<8;j++){
        unsigned long long ad0 = *(const unsigned long long*)&As2[k][2*(ty*8+j)];
        unsigned long long ad1 = *(const unsigned long long*)&As2[k][128 + 2*(ty*8+j)];
        ffma2(acc[0][j], wv.x, ad0);
        ffma2(acc[1][j], wv.y, ad0);
        ffma2(acc[2][j], wv.x, ad1);
        ffma2(acc[3][j], wv.y, ad1);
      }
    }
  }
  float4 bo = *(const float4*)&bias[o0 + tx*4];
#pragma unroll
  for(int g=0;g<2;g++){
#pragma unroll
    for(int j=0;j<8;j++){
      int t = t0 + g*64 + ty*8 + j;
      float* hrow = g_h + ((size_t)b*Qc + t)*Hc + o0 + tx*4;
      float4 h = *(float4*)hrow;
      float2 p0 = unpk(acc[2*g][j]);
      float2 p1 = unpk(acc[2*g+1][j]);
      h.x += p0.x + bo.x;
      h.y += p0.y + bo.y;
      h.z += p1.x + bo.z;
      h.w += p1.y + bo.w;
      *(float4*)hrow = h;
    }
  }
}

// ============ 7) Kalman precompute with fused output-LN ============
__global__ void __launch_bounds__(256) k_scanprep(const float* __restrict__ olnw,
                                                  const float* __restrict__ olnb,
                                                  const float* __restrict__ rpw,
                                                  const float* __restrict__ rpb,
                                                  const float* __restrict__ gw,
                                                  const float* __restrict__ gb){
  int t0 = blockIdx.x*16, b = blockIdx.y;
  __shared__ float Hs[16][193];
  __shared__ float Ws[34][193];
  __shared__ float bs[34];
  __shared__ float outs[16][34];
  int tid = threadIdx.x;
  for(int e=tid; e<16*Hc; e+=256){
    int t = e/Hc, h = e%Hc;
    Hs[t][h] = g_h[((size_t)b*Qc + t0 + t)*Hc + h];
  }
  for(int e=tid; e<34*Hc; e+=256){
    int j = e/Hc, h = e%Hc;
    Ws[j][h] = (j<2) ? rpw[j*Hc + h] : gw[(j-2)*Hc + h];
  }
  if(tid<34) bs[tid] = (tid<2) ? rpb[tid] : gb[tid-2];
  __syncthreads();
  // fused output LN (identical reduction order to the old k_outln)
  {
    int w = tid>>5, lane = tid&31;
    for(int rep=0; rep<2; rep++){
      int t = w + rep*8;
      float v[6]; float s = 0.f;
#pragma unroll
      for(int j=0;j<6;j++){ v[j] = Hs[t][lane+32*j]; s += v[j]; }
      s = wred(s);
      float m = s*(1.f/192.f);
      float sq = 0.f;
#pragma unroll
      for(int j=0;j<6;j++){ float d = v[j]-m; sq += d*d; }
      sq = wred(sq);
      float rstd = rsqrtf(sq*(1.f/192.f) + 1e-5f);
#pragma unroll
      for(int j=0;j<6;j++){
        int c = lane+32*j;
        Hs[t][c] = (v[j]-m)*rstd*olnw[c] + olnb[c];
      }
    }
  }
  __syncthreads();
  if(t0 == Qc-16){
    for(int e=tid; e<Hc; e+=256)
      g_hseq[((size_t)b*Qc + (Qc-1))*Hc + e] = Hs[15][e];
  }
  for(int e=tid; e<16*34; e+=256){
    int t = e/34, j = e%34;
    float acc = bs[j];
    for(int h=0;h<Hc;h++) acc += Hs[t][h]*Ws[j][h];
    float v;
    if(j==0)      v = 1.25f*sigm(acc);
    else if(j==1) v = PI_F*tanhf(acc);
    else          v = sigm(acc);
    outs[t][j] = v;
  }
  __syncthreads();
  if(tid<16){
    float rho = outs[tid][0], phi = outs[tid][1];
    float sn, cs; sincosf(phi, &sn, &cs);
    outs[tid][0] = rho*cs;
    outs[tid][1] = rho*sn;
  }
  __syncthreads();
  for(int e=tid; e<16*34; e+=256){
    int t = e/34, j = e%34;
    g_rpg[((size_t)b*Qc + t0 + t)*34 + j] = outs[t][j];
  }
}

// ============ 8) sequential Kalman scan ============
__global__ void k_scan(const float* __restrict__ x){
  int b = blockIdx.x, d = threadIdx.x;
  const float* xb = x + (size_t)b*Qc*Dc;
  const float* rp = g_rpg + (size_t)b*Qc*34;
  float xp = xb[d];
  float sign = (d<16) ? -1.f : 1.f;
  float rc = rp[0], rs = rp[1], gn = rp[2+d], y = xb[d];
  for(int t=0;t<Qc;t++){
    float nrc=0.f, nrs=0.f, ngn=0.f, ny=0.f;
    if(t+1<Qc){
      const float* r = rp + (size_t)(t+1)*34;
      nrc = r[0]; nrs = r[1]; ngn = r[2+d];
      ny = xb[(size_t)(t+1)*Dc + d];
    }
    float other = __shfl_xor_sync(0xffffffffu, xp, 16);
    float xpri = rc*xp + sign*rs*other;
    xp = xpri + gn*(y - xpri);
    rc=nrc; rs=nrs; gn=ngn; y=ny;
  }
  g_xpost[b*Dc + d] = xp;
}

// ============ 9) rollout init ============
__global__ void k_rollinit(){
  int b = blockIdx.x, h = threadIdx.x;
  if(b==0 && h==0){ g_cnt = 0u; g_gen = 0u; }
  g_hr[b*Hc + h] = g_hseq[((size_t)b*Qc + (Qc-1))*Hc + h];
  if(h<Dc) g_curr[b*Dc + h] = g_xpost[b*Dc + h];
}

__device__ __forceinline__ void gridbar(unsigned NB){
  __threadfence();
  __syncthreads();
  if(threadIdx.x==0){
    unsigned gen = g_gen;
    if(atomicAdd(&g_cnt, 1u) == NB-1u){
      g_cnt = 0u;
      __threadfence();
      g_gen = gen + 1u;
    } else {
      while(g_gen == gen) __nanosleep(64);
    }
    __threadfence();
  }
  __syncthreads();
}

// ============ 10) persistent rollout ============
__global__ void __launch_bounds__(256) k_roll(const float* __restrict__ riW,
                                              const float* __restrict__ riB,
                                              const float* __restrict__ whh,
                                              const float* __restrict__ bhh,
                                              const float* __restrict__ wih,
                                              const float* __restrict__ bih,
                                              const float* __restrict__ lnw,
                                              const float* __restrict__ lnb,
                                              const float* __restrict__ rpw,
                                              const float* __restrict__ rpb,
                                              float* __restrict__ dout){
  __shared__ float In[32][33];
  __shared__ __align__(16) float Wt[32][68];
  __shared__ float red[12];
  __shared__ float curs[Dc];
  int tid = threadIdx.x;
  unsigned NB = gridDim.x;
  for(int step=0; step<WOUTc; step++){
    {
      int u = blockIdx.x;
      if(u < 96){
        int ox = u%12, by = u/12;
        bool xpath = ox<3;
        int o0 = xpath? ox*64 : (ox-3)*64;
        int b0 = by*32;
        int K  = xpath? (Hc+Dc) : Hc;
        const float* W = xpath? riW : whh;
        int tb = tid&15, to = tid>>4;
        float acc[2][4] = {};
        int nch = K/32;
        for(int ch=0; ch<nch; ch++){
          int c0 = ch*32;
          __syncthreads();
          for(int e=tid; e<1024; e+=256){
            int bb = e>>5, k = e&31;
            float v;
            if(xpath && ch==6) v = __ldcg(&g_curr[(b0+bb)*Dc + k]);
            else               v = __ldcg(&g_hr[(b0+bb)*Hc + c0 + k]);
            In[k][bb] = v;
          }
          for(int e=tid; e<2048; e+=256){
            int o = e>>5, k = e&31;
            Wt[k][o] = W[(size_t)(o0+o)*K + c0 + k];
          }
          __syncthreads();
#pragma unroll
          for(int k=0;k<32;k++){
            float a0 = In[k][tb*2], a1 = In[k][tb*2+1];
            float4 w = *(const float4*)&Wt[k][to<<2];
            acc[0][0]+=a0*w.x; acc[0][1]+=a0*w.y; acc[0][2]+=a0*w.z; acc[0][3]+=a0*w.w;
            acc[1][0]+=a1*w.x; acc[1][1]+=a1*w.y; acc[1][2]+=a1*w.z; acc[1][3]+=a1*w.w;
          }
        }
#pragma unroll
        for(int i=0;i<2;i++){
          int b = b0 + tb*2 + i;
#pragma unroll
          for(int j=0;j<4;j++){
            int o = o0 + (to<<2) + j;
            float v = acc[i][j];
            if(xpath) __stcg(&g_xr[b*Hc + o], tanhf(v + riB[o]));
            else      __stcg(&g_gh[b*3*Hc + o], v + bhh[o]);
          }
        }
      }
    }
    gridbar(NB);
    {
      int u = blockIdx.x;
      if(u < 72){
        int o0 = (u%9)*64, b0 = (u/9)*32;
        int tb = tid&15, to = tid>>4;
        float acc[2][4] = {};
        for(int ch=0; ch<6; ch++){
          int c0 = ch*32;
          __syncthreads();
          for(int e=tid; e<1024; e+=256){
            int bb = e>>5, k = e&31;
            In[k][bb] = __ldcg(&g_xr[(b0+bb)*Hc + c0 + k]);
          }
          for(int e=tid; e<2048; e+=256){
            int o = e>>5, k = e&31;
            Wt[k][o] = wih[(size_t)(o0+o)*Hc + c0 + k];
          }
          __syncthreads();
#pragma unroll
          for(int k=0;k<32;k++){
            float a0 = In[k][tb*2], a1 = In[k][tb*2+1];
            float4 w = *(const float4*)&Wt[k][to<<2];
            acc[0][0]+=a0*w.x; acc[0][1]+=a0*w.y; acc[0][2]+=a0*w.z; acc[0][3]+=a0*w.w;
            acc[1][0]+=a1*w.x; acc[1][1]+=a1*w.y; acc[1][2]+=a1*w.z; acc[1][3]+=a1*w.w;
          }
        }
#pragma unroll
        for(int i=0;i<2;i++){
          int b = b0 + tb*2 + i;
#pragma unroll
          for(int j=0;j<4;j++){
            int o = o0 + (to<<2) + j;
            __stcg(&g_gi[b*3*Hc + o], acc[i][j] + bih[o]);
          }
        }
      }
    }
    gridbar(NB);
    for(int rep=0; rep<2; rep++){
      int b = blockIdx.x + rep*128;
      int o = tid;
      bool act = o < Hc;
      int w = o>>5, lane = o&31;
      float v = 0.f, hr = 0.f;
      if(act){
        float gi0 = __ldcg(&g_gi[b*576 + o]),       gh0 = __ldcg(&g_gh[b*576 + o]);
        float gi1 = __ldcg(&g_gi[b*576 + 192 + o]), gh1 = __ldcg(&g_gh[b*576 + 192 + o]);
        float gi2 = __ldcg(&g_gi[b*576 + 384 + o]), gh2 = __ldcg(&g_gh[b*576 + 384 + o]);
        hr = __ldcg(&g_hr[b*Hc + o]);
        float r = sigm(gi0 + gh0);
        float z = sigm(gi1 + gh1);
        float n = tanhf(gi2 + r*gh2);
        v = (1.f - z)*n + z*hr;
      }
      if(o<Dc) curs[o] = __ldcg(&g_curr[b*Dc + o]);
      float s = wred(act? v : 0.f);
      if(lane==0 && w<6) red[w] = s;
      __syncthreads();
      float m = (red[0]+red[1]+red[2]+red[3]+red[4]+red[5])*(1.f/192.f);
      __syncthreads();
      float d0 = act? (v - m) : 0.f;
      s = wred(d0*d0);
      if(lane==0 && w<6) red[w] = s;
      __syncthreads();
      float var = (red[0]+red[1]+red[2]+red[3]+red[4]+red[5])*(1.f/192.f);
      float hn = 0.f;
      if(act){
        hn = d0*rsqrtf(var + 1e-5f)*lnw[o] + lnb[o];
        __stcg(&g_hr[b*Hc + o], hn);
      }
      __syncthreads();
      float s0 = wred(act? hn*rpw[o] : 0.f);
      float s1 = wred(act? hn*rpw[Hc + o] : 0.f);
      if(lane==0 && w<6){ red[w] = s0; red[6+w] = s1; }
      __syncthreads();
      float p0 = red[0]+red[1]+red[2]+red[3]+red[4]+red[5] + rpb[0];
      float p1 = red[6]+red[7]+red[8]+red[9]+red[10]+red[11] + rpb[1];
      float rho = 1.25f*sigm(p0);
      float phi = PI_F*tanhf(p1);
      float sn, cs; sincosf(phi, &sn, &cs);
      float rc = rho*cs, rs = rho*sn;
      if(o<Dc){
        float self = curs[o];
        float other = curs[o^16];
        float outv = rc*self + ((o<16)? -rs : rs)*other;
        __stcg(&g_curr[b*Dc + o], outv);
        dout[((size_t)b*WOUTc + step)*Dc + o] = outv;
      }
      __syncthreads();
    }
    gridbar(NB);
  }
}

// ============================== launch ==============================
extern "C" void kernel_launch(void* const* d_in, const int* in_sizes, int n_in,
                              void* d_out, int out_size){
  const float* x_in    = (const float*)d_in[0];
  const float* inp_w   = (const float*)d_in[1];
  const float* inp_b   = (const float*)d_in[2];
  const float* b_dw_w  = (const float*)d_in[3];
  const float* b_dw_b  = (const float*)d_in[4];
  const float* b_ln_w  = (const float*)d_in[5];
  const float* b_ln_b  = (const float*)d_in[6];
  const float* b_pw1_w = (const float*)d_in[7];
  const float* b_pw1_b = (const float*)d_in[8];
  const float* b_grn_g = (const float*)d_in[9];
  const float* b_grn_b = (const float*)d_in[10];
  const float* b_pw2_w = (const float*)d_in[11];
  const float* b_pw2_b = (const float*)d_in[12];
  const float* out_ln_w= (const float*)d_in[13];
  const float* out_ln_b= (const float*)d_in[14];
  const float* fc_rp_w = (const float*)d_in[15];
  const float* fc_rp_b = (const float*)d_in[16];
  const float* fc_gain_w=(const float*)d_in[17];
  const float* fc_gain_b=(const float*)d_in[18];
  const float* roll_in_w=(const float*)d_in[19];
  const float* roll_in_b=(const float*)d_in[20];
  const float* gru_wih = (const float*)d_in[21];
  const float* gru_whh = (const float*)d_in[22];
  const float* gru_bih = (const float*)d_in[23];
  const float* gru_bhh = (const float*)d_in[24];
  const float* roll_ln_w=(const float*)d_in[25];
  const float* roll_ln_b=(const float*)d_in[26];
  const float* fc_rp_r_w=(const float*)d_in[27];
  const float* fc_rp_r_b=(const float*)d_in[28];
  float* dout = (float*)d_out;

  k_featproj<<<dim3(Qc/64, Hc/64, Bc), 256>>>(x_in, inp_w, inp_b);

  for(int i=0;i<2;i++){
    k_dwconv_ln<<<dim3(Qc/16, Bc), 256>>>(b_dw_w + (size_t)i*Hc*KERc,
                                          b_dw_b + (size_t)i*Hc,
                                          b_ln_w + (size_t)i*Hc,
                                          b_ln_b + (size_t)i*Hc);
    k_pw1x<<<dim3(Qc/128, HIDc/64, Bc), 128>>>(b_pw1_w + (size_t)i*HIDc*Hc,
                                               b_pw1_b + (size_t)i*HIDc);
    k_grn_scale<<<Bc, HIDc>>>(b_grn_g + (size_t)i*HIDc);
    k_pw2x<<<dim3(Qc/128, Hc/64, Bc), 128>>>(b_pw2_w + (size_t)i*Hc*HIDc,
                                             b_pw2_b + (size_t)i*Hc,
                                             b_grn_b + (size_t)i*HIDc);
  }

  k_scanprep<<<dim3(Qc/16, Bc), 256>>>(out_ln_w, out_ln_b,
                                       fc_rp_w, fc_rp_b, fc_gain_w, fc_gain_b);
  k_scan<<<Bc, 32>>>(x_in);
  k_rollinit<<<Bc, Hc>>>();

  k_roll<<<128, 256>>>(roll_in_w, roll_in_b, gru_whh, gru_bhh,
                       gru_wih, gru_bih, roll_ln_w, roll_ln_b,
                       fc_rp_r_w, fc_rp_r_b, dout);
}

// round 14
// speedup vs baseline: 1.0769x; 1.0769x over previous
#include <cuda_runtime.h>
#include <cuda_bf16.h>
#include <math.h>
#include <stdint.h>

#define Bc 256
#define Qc 512
#define Dc 32
#define Hc 192
#define HIDc 384
#define INCHc 96
#define KERc 9
#define WOUTc 64
#define PI_F 3.14159265358979f

// ---------------- scratch (all fp32 — trunk precision is load-bearing) ----------------
__device__ __align__(16) float g_h   [(size_t)Bc*Qc*Hc];    // residual (B,Q,H)
__device__ __align__(16) float g_af  [(size_t)Bc*Qc*Hc];    // LN'd act (B,Q,H)
__device__ __align__(16) float g_midf[(size_t)Bc*Qc*HIDc];  // pw1 out  (B,Q,HID)
__device__ __align__(16) float g_hseq[(size_t)Bc*Qc*Hc];    // only t=511 rows used
__device__ float g_gxsq[Bc*HIDc];
__device__ float g_scale[Bc*HIDc];
__device__ float g_rpg [(size_t)Bc*Qc*34];
__device__ float g_xpost[Bc*Dc];
__device__ float g_hr  [Bc*Hc];
__device__ float g_xr  [Bc*Hc];
__device__ float g_gi  [Bc*3*Hc];
__device__ float g_gh  [Bc*3*Hc];
__device__ float g_curr[Bc*Dc];
__device__ unsigned g_cnt;
__device__ volatile unsigned g_gen;

// ---------------- helpers ----------------
__device__ __forceinline__ float sigm(float x){ return 1.f/(1.f+expf(-x)); }
__device__ __forceinline__ float gelu_exact(float x){ return 0.5f*x*(1.f+erff(x*0.70710678118654752f)); }
__device__ __forceinline__ float wred(float v){
#pragma unroll
  for(int s=16;s;s>>=1) v += __shfl_xor_sync(0xffffffffu, v, s);
  return v;
}
__device__ __forceinline__ unsigned long long dupf(float w){
  unsigned long long r;
  asm("mov.b64 %0, {%1, %1};" : "=l"(r) : "f"(w));
  return r;
}
__device__ __forceinline__ void ffma2(unsigned long long &acc, unsigned long long a, unsigned long long b){
  asm("fma.rn.f32x2 %0, %1, %2, %0;" : "+l"(acc) : "l"(a), "l"(b));
}
__device__ __forceinline__ float2 unpk(unsigned long long p){
  float2 f; asm("mov.b64 {%0, %1}, %2;" : "=f"(f.x), "=f"(f.y) : "l"(p));
  return f;
}

// ============ 1) features + input projection -> g_h (B,Q,H) ============
__global__ void __launch_bounds__(256) k_featproj(const float* __restrict__ x,
                                                  const float* __restrict__ W,
                                                  const float* __restrict__ bias){
  int t0 = blockIdx.x*64, o0 = blockIdx.y*64, b = blockIdx.z;
  __shared__ __align__(16) float Xs[66][33];
  __shared__ __align__(16) float As[32][64];
  __shared__ __align__(16) float Ws[32][68];
  int tid = threadIdx.x;
  for(int e=tid; e<66*32; e+=256){
    int i = e>>5, d = e&31;
    int tg = t0 - 2 + i;
    float v = 0.f;
    if(tg>=0 && tg<Qc) v = x[((size_t)b*Qc + tg)*Dc + d];
    Xs[i][d] = v;
  }
  int tx = tid & 15, ty = tid >> 4;
  float acc[4][4] = {};
  for(int j=0;j<3;j++){
    __syncthreads();
    for(int e=tid; e<2048; e+=256){
      int k = e>>6, t = e&63;
      int tg = t0+t;
      float x0 = Xs[t+2][k], x1 = Xs[t+1][k], x2 = Xs[t][k];
      float v;
      if(j==0)      v = x0;
      else if(j==1) v = (tg>=1)? x0-x1 : 0.f;
      else          v = (tg>=2)? (x0-2.f*x1+x2) : ((tg==1)? x0-x1 : 0.f);
      As[k][t] = v;
    }
    for(int e=tid; e<2048; e+=256){
      int o = e>>5, k = e&31;
      Ws[k][o] = W[(size_t)(o0+o)*INCHc + j*32 + k];
    }
    __syncthreads();
#pragma unroll
    for(int k=0;k<32;k++){
      float4 a = *(const float4*)&As[k][tx<<2];
      float4 w = *(const float4*)&Ws[k][ty<<2];
      acc[0][0]+=w.x*a.x; acc[0][1]+=w.x*a.y; acc[0][2]+=w.x*a.z; acc[0][3]+=w.x*a.w;
      acc[1][0]+=w.y*a.x; acc[1][1]+=w.y*a.y; acc[1][2]+=w.y*a.z; acc[1][3]+=w.y*a.w;
      acc[2][0]+=w.z*a.x; acc[2][1]+=w.z*a.y; acc[2][2]+=w.z*a.z; acc[2][3]+=w.z*a.w;
      acc[3][0]+=w.w*a.x; acc[3][1]+=w.w*a.y; acc[3][2]+=w.w*a.z; acc[3][3]+=w.w*a.w;
    }
  }
  float4 bo = *(const float4*)&bias[o0 + (ty<<2)];
#pragma unroll
  for(int jj=0;jj<4;jj++){
    int t = t0 + (tx<<2) + jj;
    float4 v;
    v.x = acc[0][jj] + bo.x;
    v.y = acc[1][jj] + bo.y;
    v.z = acc[2][jj] + bo.z;
    v.w = acc[3][jj] + bo.w;
    *(float4*)&g_h[((size_t)b*Qc + t)*Hc + o0 + (ty<<2)] = v;
  }
}

// ============ 2) dwconv (k=9 edge pad) + LN -> g_af fp32 (B,Q,H); zero gxsq ============
__global__ void __launch_bounds__(256) k_dwconv_ln(const float* __restrict__ dww,
                                                   const float* __restrict__ dwb,
                                                   const float* __restrict__ lnw,
                                                   const float* __restrict__ lnb){
  int t0 = blockIdx.x*16, b = blockIdx.y;
  __shared__ __align__(16) float In[24][Hc];
  __shared__ __align__(16) float Outp[16][Hc];
  __shared__ float Wd[Hc*KERc];
  __shared__ float Bd[Hc], Lw[Hc], Lb[Hc];
  int tid = threadIdx.x;
  if(blockIdx.x==0){
    for(int e=tid; e<HIDc; e+=256) g_gxsq[b*HIDc+e] = 0.f;
  }
  for(int e=tid; e<24*48; e+=256){
    int i = e/48, q = e%48;
    int tg = t0 - 4 + i;
    tg = tg < 0 ? 0 : (tg > Qc-1 ? Qc-1 : tg);
    *(float4*)&In[i][q*4] = *(const float4*)&g_h[((size_t)b*Qc + tg)*Hc + q*4];
  }
  for(int e=tid; e<Hc*KERc; e+=256) Wd[e] = dww[e];
  for(int e=tid; e<Hc; e+=256){ Bd[e] = dwb[e]; Lw[e] = lnw[e]; Lb[e] = lnb[e]; }
  __syncthreads();
  for(int e=tid; e<16*Hc; e+=256){
    int t = e/Hc, c = e%Hc;
    float acc = Bd[c];
#pragma unroll
    for(int k=0;k<KERc;k++) acc += In[t+k][c]*Wd[c*KERc+k];
    Outp[t][c] = acc;
  }
  __syncthreads();
  int w = tid>>5, lane = tid&31;
  for(int rep=0; rep<2; rep++){
    int t = w + rep*8;
    float v[6]; float s = 0.f;
#pragma unroll
    for(int j=0;j<6;j++){ v[j] = Outp[t][lane+32*j]; s += v[j]; }
    s = wred(s);
    float m = s*(1.f/192.f);
    float sq = 0.f;
#pragma unroll
    for(int j=0;j<6;j++){ float d = v[j]-m; sq += d*d; }
    sq = wred(sq);
    float rstd = rsqrtf(sq*(1.f/192.f) + 1e-5f);
#pragma unroll
    for(int j=0;j<6;j++){
      int c = lane+32*j;
      Outp[t][c] = (v[j]-m)*rstd*Lw[c] + Lb[c];
    }
  }
  __syncthreads();
  for(int e=tid; e<16*48; e+=256){
    int t = e/48, q = e%48;
    *(float4*)&g_af[((size_t)b*Qc + t0 + t)*Hc + q*4] = *(float4*)&Outp[t][q*4];
  }
}

// ============ 3) pw1: f32x2 GEMM (M=128 t, N=64 o, K=192) + bias + GELU + fused gx ============
__global__ void __launch_bounds__(128,4) k_pw1x(const float* __restrict__ W,
                                                const float* __restrict__ bias){
  __shared__ __align__(16) float As[32][132];
  __shared__ __align__(16) float Ws[32][68];
  __shared__ float osq[64];
  int t0 = blockIdx.x*128, o0 = blockIdx.y*64, b = blockIdx.z;
  int tid = threadIdx.x, tx = tid&15, ty = tid>>4;  // ty 0..7
  if(tid<64) osq[tid] = 0.f;
  unsigned long long acc[4][8] = {};
  const float* Ag = g_af + ((size_t)b*Qc + t0)*Hc;
  for(int c0=0;c0<Hc;c0+=32){
    __syncthreads();
    for(int e=tid;e<1024;e+=128){
      int kq=e&7, t=e>>3;
      float4 v = *(const float4*)&Ag[(size_t)t*Hc + c0 + kq*4];
      As[kq*4+0][t]=v.x; As[kq*4+1][t]=v.y; As[kq*4+2][t]=v.z; As[kq*4+3][t]=v.w;
    }
    for(int e=tid;e<512;e+=128){
      int o=e>>3, kq=e&7;
      float4 w = *(const float4*)&W[(size_t)(o0+o)*Hc + c0 + kq*4];
      Ws[kq*4+0][o]=w.x; Ws[kq*4+1][o]=w.y; Ws[kq*4+2][o]=w.z; Ws[kq*4+3][o]=w.w;
    }
    __syncthreads();
#pragma unroll 8
    for(int k=0;k<32;k++){
      ulonglong2 wv = *(const ulonglong2*)&Ws[k][tx*4];
#pragma unroll
      for(int j=0;j<8;j++){
        unsigned long long ad0 = dupf(As[k][ty*8+j]);
        unsigned long long ad1 = dupf(As[k][64+ty*8+j]);
        ffma2(acc[0][j], wv.x, ad0);
        ffma2(acc[1][j], wv.y, ad0);
        ffma2(acc[2][j], wv.x, ad1);
        ffma2(acc[3][j], wv.y, ad1);
      }
    }
  }
  float4 bo = *(const float4*)&bias[o0 + tx*4];
  float sq[4] = {};
#pragma unroll
  for(int g=0;g<2;g++){
#pragma unroll
    for(int j=0;j<8;j++){
      int t = t0 + g*64 + ty*8 + j;
      float2 p0 = unpk(acc[2*g][j]);
      float2 p1 = unpk(acc[2*g+1][j]);
      float4 v;
      v.x = gelu_exact(p0.x + bo.x);
      v.y = gelu_exact(p0.y + bo.y);
      v.z = gelu_exact(p1.x + bo.z);
      v.w = gelu_exact(p1.y + bo.w);
      sq[0]+=v.x*v.x; sq[1]+=v.y*v.y; sq[2]+=v.z*v.z; sq[3]+=v.w*v.w;
      *(float4*)&g_midf[((size_t)b*Qc + t)*HIDc + o0 + tx*4] = v;
    }
  }
  atomicAdd(&osq[tx*4+0], sq[0]);
  atomicAdd(&osq[tx*4+1], sq[1]);
  atomicAdd(&osq[tx*4+2], sq[2]);
  atomicAdd(&osq[tx*4+3], sq[3]);
  __syncthreads();
  if(tid<64) atomicAdd(&g_gxsq[b*HIDc + o0 + tid], osq[tid]);
}

// ============ 4) GRN scale ============
__global__ void k_grn_scale(const float* __restrict__ gg){
  int b = blockIdx.x, o = threadIdx.x;
  int w = o>>5, lane = o&31;
  float v = sqrtf(g_gxsq[b*HIDc + o]);
  float s = wred(v);
  __shared__ float red[12];
  if(lane==0) red[w] = s;
  __syncthreads();
  float tot = 0.f;
#pragma unroll
  for(int i=0;i<12;i++) tot += red[i];
  float mean = tot*(1.f/384.f);
  g_scale[b*HIDc + o] = 1.f + gg[o]*v/(mean + 1e-6f);
}

// ============ 5) pw2: f32x2 GEMM (M=128 t, N=64 o, K=384) on GRN-transformed y + residual ============
__global__ void __launch_bounds__(128,4) k_pw2x(const float* __restrict__ W,
                                                const float* __restrict__ bias,
                                                const float* __restrict__ grnb){
  __shared__ __align__(16) float As[32][132];
  __shared__ __align__(16) float Ws[32][68];
  __shared__ float sc_s[HIDc], gb_s[HIDc];
  int t0 = blockIdx.x*128, o0 = blockIdx.y*64, b = blockIdx.z;
  int tid = threadIdx.x, tx = tid&15, ty = tid>>4;
  for(int e=tid; e<HIDc; e+=128){ sc_s[e] = g_scale[b*HIDc+e]; gb_s[e] = grnb[e]; }
  unsigned long long acc[4][8] = {};
  const float* Ag = g_midf + ((size_t)b*Qc + t0)*HIDc;
  for(int c0=0;c0<HIDc;c0+=32){
    __syncthreads();
    for(int e=tid;e<1024;e+=128){
      int kq=e&7, t=e>>3;
      int c = c0 + kq*4;
      float4 m = *(const float4*)&Ag[(size_t)t*HIDc + c];
      As[kq*4+0][t] = m.x*sc_s[c+0] + gb_s[c+0];
      As[kq*4+1][t] = m.y*sc_s[c+1] + gb_s[c+1];
      As[kq*4+2][t] = m.z*sc_s[c+2] + gb_s[c+2];
      As[kq*4+3][t] = m.w*sc_s[c+3] + gb_s[c+3];
    }
    for(int e=tid;e<512;e+=128){
      int o=e>>3, kq=e&7;
      float4 w = *(const float4*)&W[(size_t)(o0+o)*HIDc + c0 + kq*4];
      Ws[kq*4+0][o]=w.x; Ws[kq*4+1][o]=w.y; Ws[kq*4+2][o]=w.z; Ws[kq*4+3][o]=w.w;
    }
    __syncthreads();
#pragma unroll 8
    for(int k=0;k<32;k++){
      ulonglong2 wv = *(const ulonglong2*)&Ws[k][tx*4];
#pragma unroll
      for(int j=0;j<8;j++){
        unsigned long long ad0 = dupf(As[k][ty*8+j]);
        unsigned long long ad1 = dupf(As[k][64+ty*8+j]);
        ffma2(acc[0][j], wv.x, ad0);
        ffma2(acc[1][j], wv.y, ad0);
        ffma2(acc[2][j], wv.x, ad1);
        ffma2(acc[3][j], wv.y, ad1);
      }
    }
  }
  float4 bo = *(const float4*)&bias[o0 + tx*4];
#pragma unroll
  for(int g=0;g<2;g++){
#pragma unroll
    for(int j=0;j<8;j++){
      int t = t0 + g*64 + ty*8 + j;
      float* hrow = g_h + ((size_t)b*Qc + t)*Hc + o0 + tx*4;
      float4 h = *(float4*)hrow;
      float2 p0 = unpk(acc[2*g][j]);
      float2 p1 = unpk(acc[2*g+1][j]);
      h.x += p0.x + bo.x;
      h.y += p0.y + bo.y;
      h.z += p1.x + bo.z;
      h.w += p1.y + bo.w;
      *(float4*)hrow = h;
    }
  }
}

// ============ 7) Kalman precompute with fused output-LN ============
__global__ void __launch_bounds__(256) k_scanprep(const float* __restrict__ olnw,
                                                  const float* __restrict__ olnb,
                                                  const float* __restrict__ rpw,
                                                  const float* __restrict__ rpb,
                                                  const float* __restrict__ gw,
                                                  const float* __restrict__ gb){
  int t0 = blockIdx.x*16, b = blockIdx.y;
  __shared__ float Hs[16][193];
  __shared__ float Ws[34][193];
  __shared__ float bs[34];
  __shared__ float outs[16][34];
  int tid = threadIdx.x;
  for(int e=tid; e<16*Hc; e+=256){
    int t = e/Hc, h = e%Hc;
    Hs[t][h] = g_h[((size_t)b*Qc + t0 + t)*Hc + h];
  }
  for(int e=tid; e<34*Hc; e+=256){
    int j = e/Hc, h = e%Hc;
    Ws[j][h] = (j<2) ? rpw[j*Hc + h] : gw[(j-2)*Hc + h];
  }
  if(tid<34) bs[tid] = (tid<2) ? rpb[tid] : gb[tid-2];
  __syncthreads();
  // fused output LN (identical reduction order to the old k_outln)
  {
    int w = tid>>5, lane = tid&31;
    for(int rep=0; rep<2; rep++){
      int t = w + rep*8;
      float v[6]; float s = 0.f;
#pragma unroll
      for(int j=0;j<6;j++){ v[j] = Hs[t][lane+32*j]; s += v[j]; }
      s = wred(s);
      float m = s*(1.f/192.f);
      float sq = 0.f;
#pragma unroll
      for(int j=0;j<6;j++){ float d = v[j]-m; sq += d*d; }
      sq = wred(sq);
      float rstd = rsqrtf(sq*(1.f/192.f) + 1e-5f);
#pragma unroll
      for(int j=0;j<6;j++){
        int c = lane+32*j;
        Hs[t][c] = (v[j]-m)*rstd*olnw[c] + olnb[c];
      }
    }
  }
  __syncthreads();
  if(t0 == Qc-16){
    for(int e=tid; e<Hc; e+=256)
      g_hseq[((size_t)b*Qc + (Qc-1))*Hc + e] = Hs[15][e];
  }
  for(int e=tid; e<16*34; e+=256){
    int t = e/34, j = e%34;
    float acc = bs[j];
    for(int h=0;h<Hc;h++) acc += Hs[t][h]*Ws[j][h];
    float v;
    if(j==0)      v = 1.25f*sigm(acc);
    else if(j==1) v = PI_F*tanhf(acc);
    else          v = sigm(acc);
    outs[t][j] = v;
  }
  __syncthreads();
  if(tid<16){
    float rho = outs[tid][0], phi = outs[tid][1];
    float sn, cs; sincosf(phi, &sn, &cs);
    outs[tid][0] = rho*cs;
    outs[tid][1] = rho*sn;
  }
  __syncthreads();
  for(int e=tid; e<16*34; e+=256){
    int t = e/34, j = e%34;
    g_rpg[((size_t)b*Qc + t0 + t)*34 + j] = outs[t][j];
  }
}

// ============ 8) sequential Kalman scan ============
__global__ void k_scan(const float* __restrict__ x){
  int b = blockIdx.x, d = threadIdx.x;
  const float* xb = x + (size_t)b*Qc*Dc;
  const float* rp = g_rpg + (size_t)b*Qc*34;
  float xp = xb[d];
  float sign = (d<16) ? -1.f : 1.f;
  float rc = rp[0], rs = rp[1], gn = rp[2+d], y = xb[d];
  for(int t=0;t<Qc;t++){
    float nrc=0.f, nrs=0.f, ngn=0.f, ny=0.f;
    if(t+1<Qc){
      const float* r = rp + (size_t)(t+1)*34;
      nrc = r[0]; nrs = r[1]; ngn = r[2+d];
      ny = xb[(size_t)(t+1)*Dc + d];
    }
    float other = __shfl_xor_sync(0xffffffffu, xp, 16);
    float xpri = rc*xp + sign*rs*other;
    xp = xpri + gn*(y - xpri);
    rc=nrc; rs=nrs; gn=ngn; y=ny;
  }
  g_xpost[b*Dc + d] = xp;
}

// ============ 9) rollout init ============
__global__ void k_rollinit(){
  int b = blockIdx.x, h = threadIdx.x;
  if(b==0 && h==0){ g_cnt = 0u; g_gen = 0u; }
  g_hr[b*Hc + h] = g_hseq[((size_t)b*Qc + (Qc-1))*Hc + h];
  if(h<Dc) g_curr[b*Dc + h] = g_xpost[b*Dc + h];
}

__device__ __forceinline__ void gridbar(unsigned NB){
  __threadfence();
  __syncthreads();
  if(threadIdx.x==0){
    unsigned gen = g_gen;
    if(atomicAdd(&g_cnt, 1u) == NB-1u){
      g_cnt = 0u;
      __threadfence();
      g_gen = gen + 1u;
    } else {
      while(g_gen == gen) __nanosleep(64);
    }
    __threadfence();
  }
  __syncthreads();
}

// ============ 10) persistent rollout ============
__global__ void __launch_bounds__(256) k_roll(const float* __restrict__ riW,
                                              const float* __restrict__ riB,
                                              const float* __restrict__ whh,
                                              const float* __restrict__ bhh,
                                              const float* __restrict__ wih,
                                              const float* __restrict__ bih,
                                              const float* __restrict__ lnw,
                                              const float* __restrict__ lnb,
                                              const float* __restrict__ rpw,
                                              const float* __restrict__ rpb,
                                              float* __restrict__ dout){
  __shared__ float In[32][33];
  __shared__ __align__(16) float Wt[32][68];
  __shared__ float red[12];
  __shared__ float curs[Dc];
  int tid = threadIdx.x;
  unsigned NB = gridDim.x;
  for(int step=0; step<WOUTc; step++){
    {
      int u = blockIdx.x;
      if(u < 96){
        int ox = u%12, by = u/12;
        bool xpath = ox<3;
        int o0 = xpath? ox*64 : (ox-3)*64;
        int b0 = by*32;
        int K  = xpath? (Hc+Dc) : Hc;
        const float* W = xpath? riW : whh;
        int tb = tid&15, to = tid>>4;
        float acc[2][4] = {};
        int nch = K/32;
        for(int ch=0; ch<nch; ch++){
          int c0 = ch*32;
          __syncthreads();
          for(int e=tid; e<1024; e+=256){
            int bb = e>>5, k = e&31;
            float v;
            if(xpath && ch==6) v = __ldcg(&g_curr[(b0+bb)*Dc + k]);
            else               v = __ldcg(&g_hr[(b0+bb)*Hc + c0 + k]);
            In[k][bb] = v;
          }
          for(int e=tid; e<2048; e+=256){
            int o = e>>5, k = e&31;
            Wt[k][o] = W[(size_t)(o0+o)*K + c0 + k];
          }
          __syncthreads();
#pragma unroll
          for(int k=0;k<32;k++){
            float a0 = In[k][tb*2], a1 = In[k][tb*2+1];
            float4 w = *(const float4*)&Wt[k][to<<2];
            acc[0][0]+=a0*w.x; acc[0][1]+=a0*w.y; acc[0][2]+=a0*w.z; acc[0][3]+=a0*w.w;
            acc[1][0]+=a1*w.x; acc[1][1]+=a1*w.y; acc[1][2]+=a1*w.z; acc[1][3]+=a1*w.w;
          }
        }
#pragma unroll
        for(int i=0;i<2;i++){
          int b = b0 + tb*2 + i;
#pragma unroll
          for(int j=0;j<4;j++){
            int o = o0 + (to<<2) + j;
            float v = acc[i][j];
            if(xpath) __stcg(&g_xr[b*Hc + o], tanhf(v + riB[o]));
            else      __stcg(&g_gh[b*3*Hc + o], v + bhh[o]);
          }
        }
      }
    }
    gridbar(NB);
    {
      int u = blockIdx.x;
      if(u < 72){
        int o0 = (u%9)*64, b0 = (u/9)*32;
        int tb = tid&15, to = tid>>4;
        float acc[2][4] = {};
        for(int ch=0; ch<6; ch++){
          int c0 = ch*32;
          __syncthreads();
          for(int e=tid; e<1024; e+=256){
            int bb = e>>5, k = e&31;
            In[k][bb] = __ldcg(&g_xr[(b0+bb)*Hc + c0 + k]);
          }
          for(int e=tid; e<2048; e+=256){
            int o = e>>5, k = e&31;
            Wt[k][o] = wih[(size_t)(o0+o)*Hc + c0 + k];
          }
          __syncthreads();
#pragma unroll
          for(int k=0;k<32;k++){
            float a0 = In[k][tb*2], a1 = In[k][tb*2+1];
            float4 w = *(const float4*)&Wt[k][to<<2];
            acc[0][0]+=a0*w.x; acc[0][1]+=a0*w.y; acc[0][2]+=a0*w.z; acc[0][3]+=a0*w.w;
            acc[1][0]+=a1*w.x; acc[1][1]+=a1*w.y; acc[1][2]+=a1*w.z; acc[1][3]+=a1*w.w;
          }
        }
#pragma unroll
        for(int i=0;i<2;i++){
          int b = b0 + tb*2 + i;
#pragma unroll
          for(int j=0;j<4;j++){
            int o = o0 + (to<<2) + j;
            __stcg(&g_gi[b*3*Hc + o], acc[i][j] + bih[o]);
          }
        }
      }
    }
    gridbar(NB);
    for(int rep=0; rep<2; rep++){
      int b = blockIdx.x + rep*128;
      int o = tid;
      bool act = o < Hc;
      int w = o>>5, lane = o&31;
      float v = 0.f, hr = 0.f;
      if(act){
        float gi0 = __ldcg(&g_gi[b*576 + o]),       gh0 = __ldcg(&g_gh[b*576 + o]);
        float gi1 = __ldcg(&g_gi[b*576 + 192 + o]), gh1 = __ldcg(&g_gh[b*576 + 192 + o]);
        float gi2 = __ldcg(&g_gi[b*576 + 384 + o]), gh2 = __ldcg(&g_gh[b*576 + 384 + o]);
        hr = __ldcg(&g_hr[b*Hc + o]);
        float r = sigm(gi0 + gh0);
        float z = sigm(gi1 + gh1);
        float n = tanhf(gi2 + r*gh2);
        v = (1.f - z)*n + z*hr;
      }
      if(o<Dc) curs[o] = __ldcg(&g_curr[b*Dc + o]);
      float s = wred(act? v : 0.f);
      if(lane==0 && w<6) red[w] = s;
      __syncthreads();
      float m = (red[0]+red[1]+red[2]+red[3]+red[4]+red[5])*(1.f/192.f);
      __syncthreads();
      float d0 = act? (v - m) : 0.f;
      s = wred(d0*d0);
      if(lane==0 && w<6) red[w] = s;
      __syncthreads();
      float var = (red[0]+red[1]+red[2]+red[3]+red[4]+red[5])*(1.f/192.f);
      float hn = 0.f;
      if(act){
        hn = d0*rsqrtf(var + 1e-5f)*lnw[o] + lnb[o];
        __stcg(&g_hr[b*Hc + o], hn);
      }
      __syncthreads();
      float s0 = wred(act? hn*rpw[o] : 0.f);
      float s1 = wred(act? hn*rpw[Hc + o] : 0.f);
      if(lane==0 && w<6){ red[w] = s0; red[6+w] = s1; }
      __syncthreads();
      float p0 = red[0]+red[1]+red[2]+red[3]+red[4]+red[5] + rpb[0];
      float p1 = red[6]+red[7]+red[8]+red[9]+red[10]+red[11] + rpb[1];
      float rho = 1.25f*sigm(p0);
      float phi = PI_F*tanhf(p1);
      float sn, cs; sincosf(phi, &sn, &cs);
      float rc = rho*cs, rs = rho*sn;
      if(o<Dc){
        float self = curs[o];
        float other = curs[o^16];
        float outv = rc*self + ((o<16)? -rs : rs)*other;
        __stcg(&g_curr[b*Dc + o], outv);
        dout[((size_t)b*WOUTc + step)*Dc + o] = outv;
      }
      __syncthreads();
    }
    gridbar(NB);
  }
}

// ============================== launch ==============================
extern "C" void kernel_launch(void* const* d_in, const int* in_sizes, int n_in,
                              void* d_out, int out_size){
  const float* x_in    = (const float*)d_in[0];
  const float* inp_w   = (const float*)d_in[1];
  const float* inp_b   = (const float*)d_in[2];
  const float* b_dw_w  = (const float*)d_in[3];
  const float* b_dw_b  = (const float*)d_in[4];
  const float* b_ln_w  = (const float*)d_in[5];
  const float* b_ln_b  = (const float*)d_in[6];
  const float* b_pw1_w = (const float*)d_in[7];
  const float* b_pw1_b = (const float*)d_in[8];
  const float* b_grn_g = (const float*)d_in[9];
  const float* b_grn_b = (const float*)d_in[10];
  const float* b_pw2_w = (const float*)d_in[11];
  const float* b_pw2_b = (const float*)d_in[12];
  const float* out_ln_w= (const float*)d_in[13];
  const float* out_ln_b= (const float*)d_in[14];
  const float* fc_rp_w = (const float*)d_in[15];
  const float* fc_rp_b = (const float*)d_in[16];
  const float* fc_gain_w=(const float*)d_in[17];
  const float* fc_gain_b=(const float*)d_in[18];
  const float* roll_in_w=(const float*)d_in[19];
  const float* roll_in_b=(const float*)d_in[20];
  const float* gru_wih = (const float*)d_in[21];
  const float* gru_whh = (const float*)d_in[22];
  const float* gru_bih = (const float*)d_in[23];
  const float* gru_bhh = (const float*)d_in[24];
  const float* roll_ln_w=(const float*)d_in[25];
  const float* roll_ln_b=(const float*)d_in[26];
  const float* fc_rp_r_w=(const float*)d_in[27];
  const float* fc_rp_r_b=(const float*)d_in[28];
  float* dout = (float*)d_out;

  k_featproj<<<dim3(Qc/64, Hc/64, Bc), 256>>>(x_in, inp_w, inp_b);

  for(int i=0;i<2;i++){
    k_dwconv_ln<<<dim3(Qc/16, Bc), 256>>>(b_dw_w + (size_t)i*Hc*KERc,
                                          b_dw_b + (size_t)i*Hc,
                                          b_ln_w + (size_t)i*Hc,
                                          b_ln_b + (size_t)i*Hc);
    k_pw1x<<<dim3(Qc/128, HIDc/64, Bc), 128>>>(b_pw1_w + (size_t)i*HIDc*Hc,
                                               b_pw1_b + (size_t)i*HIDc);
    k_grn_scale<<<Bc, HIDc>>>(b_grn_g + (size_t)i*HIDc);
    k_pw2x<<<dim3(Qc/128, Hc/64, Bc), 128>>>(b_pw2_w + (size_t)i*Hc*HIDc,
                                             b_pw2_b + (size_t)i*Hc,
                                             b_grn_b + (size_t)i*HIDc);
  }

  k_scanprep<<<dim3(Qc/16, Bc), 256>>>(out_ln_w, out_ln_b,
                                       fc_rp_w, fc_rp_b, fc_gain_w, fc_gain_b);
  k_scan<<<Bc, 32>>>(x_in);
  k_rollinit<<<Bc, Hc>>>();

  k_roll<<<128, 256>>>(roll_in_w, roll_in_b, gru_whh, gru_bhh,
                       gru_wih, gru_bih, roll_ln_w, roll_ln_b,
                       fc_rp_r_w, fc_rp_r_b, dout);
}

// round 15
// speedup vs baseline: 1.0788x; 1.0018x over previous
#include <cuda_runtime.h>
#include <cuda_bf16.h>
#include <math.h>
#include <stdint.h>

#define Bc 256
#define Qc 512
#define Dc 32
#define Hc 192
#define HIDc 384
#define INCHc 96
#define KERc 9
#define WOUTc 64
#define PI_F 3.14159265358979f

// ---------------- scratch (all fp32 — trunk precision is load-bearing) ----------------
__device__ __align__(16) float g_h   [(size_t)Bc*Qc*Hc];    // residual (B,Q,H)
__device__ __align__(16) float g_af  [(size_t)Bc*Qc*Hc];    // LN'd act (B,Q,H)
__device__ __align__(16) float g_midf[(size_t)Bc*Qc*HIDc];  // pw1 out  (B,Q,HID)
__device__ __align__(16) float g_hseq[(size_t)Bc*Qc*Hc];    // only t=511 rows used
__device__ float g_gxsq[Bc*HIDc];
__device__ float g_rpg [(size_t)Bc*Qc*34];
__device__ float g_hr  [Bc*Hc];
__device__ float g_xr  [Bc*Hc];
__device__ float g_gi  [Bc*3*Hc];
__device__ float g_gh  [Bc*3*Hc];
__device__ float g_curr[Bc*Dc];
__device__ unsigned g_cnt;
__device__ volatile unsigned g_gen;

// ---------------- helpers ----------------
__device__ __forceinline__ float sigm(float x){ return 1.f/(1.f+expf(-x)); }
__device__ __forceinline__ float gelu_exact(float x){ return 0.5f*x*(1.f+erff(x*0.70710678118654752f)); }
__device__ __forceinline__ float wred(float v){
#pragma unroll
  for(int s=16;s;s>>=1) v += __shfl_xor_sync(0xffffffffu, v, s);
  return v;
}
__device__ __forceinline__ unsigned long long dupf(float w){
  unsigned long long r;
  asm("mov.b64 %0, {%1, %1};" : "=l"(r) : "f"(w));
  return r;
}
__device__ __forceinline__ void ffma2(unsigned long long &acc, unsigned long long a, unsigned long long b){
  asm("fma.rn.f32x2 %0, %1, %2, %0;" : "+l"(acc) : "l"(a), "l"(b));
}
__device__ __forceinline__ float2 unpk(unsigned long long p){
  float2 f; asm("mov.b64 {%0, %1}, %2;" : "=f"(f.x), "=f"(f.y) : "l"(p));
  return f;
}

// ============ 1) features + input projection -> g_h (B,Q,H) ============
__global__ void __launch_bounds__(256) k_featproj(const float* __restrict__ x,
                                                  const float* __restrict__ W,
                                                  const float* __restrict__ bias){
  int t0 = blockIdx.x*64, o0 = blockIdx.y*64, b = blockIdx.z;
  __shared__ __align__(16) float Xs[66][33];
  __shared__ __align__(16) float As[32][64];
  __shared__ __align__(16) float Ws[32][68];
  int tid = threadIdx.x;
  for(int e=tid; e<66*32; e+=256){
    int i = e>>5, d = e&31;
    int tg = t0 - 2 + i;
    float v = 0.f;
    if(tg>=0 && tg<Qc) v = x[((size_t)b*Qc + tg)*Dc + d];
    Xs[i][d] = v;
  }
  int tx = tid & 15, ty = tid >> 4;
  float acc[4][4] = {};
  for(int j=0;j<3;j++){
    __syncthreads();
    for(int e=tid; e<2048; e+=256){
      int k = e>>6, t = e&63;
      int tg = t0+t;
      float x0 = Xs[t+2][k], x1 = Xs[t+1][k], x2 = Xs[t][k];
      float v;
      if(j==0)      v = x0;
      else if(j==1) v = (tg>=1)? x0-x1 : 0.f;
      else          v = (tg>=2)? (x0-2.f*x1+x2) : ((tg==1)? x0-x1 : 0.f);
      As[k][t] = v;
    }
    for(int e=tid; e<2048; e+=256){
      int o = e>>5, k = e&31;
      Ws[k][o] = W[(size_t)(o0+o)*INCHc + j*32 + k];
    }
    __syncthreads();
#pragma unroll
    for(int k=0;k<32;k++){
      float4 a = *(const float4*)&As[k][tx<<2];
      float4 w = *(const float4*)&Ws[k][ty<<2];
      acc[0][0]+=w.x*a.x; acc[0][1]+=w.x*a.y; acc[0][2]+=w.x*a.z; acc[0][3]+=w.x*a.w;
      acc[1][0]+=w.y*a.x; acc[1][1]+=w.y*a.y; acc[1][2]+=w.y*a.z; acc[1][3]+=w.y*a.w;
      acc[2][0]+=w.z*a.x; acc[2][1]+=w.z*a.y; acc[2][2]+=w.z*a.z; acc[2][3]+=w.z*a.w;
      acc[3][0]+=w.w*a.x; acc[3][1]+=w.w*a.y; acc[3][2]+=w.w*a.z; acc[3][3]+=w.w*a.w;
    }
  }
  float4 bo = *(const float4*)&bias[o0 + (ty<<2)];
#pragma unroll
  for(int jj=0;jj<4;jj++){
    int t = t0 + (tx<<2) + jj;
    float4 v;
    v.x = acc[0][jj] + bo.x;
    v.y = acc[1][jj] + bo.y;
    v.z = acc[2][jj] + bo.z;
    v.w = acc[3][jj] + bo.w;
    *(float4*)&g_h[((size_t)b*Qc + t)*Hc + o0 + (ty<<2)] = v;
  }
}

// ============ 2) dwconv (k=9 edge pad) + LN -> g_af fp32 (B,Q,H); zero gxsq ============
__global__ void __launch_bounds__(256) k_dwconv_ln(const float* __restrict__ dww,
                                                   const float* __restrict__ dwb,
                                                   const float* __restrict__ lnw,
                                                   const float* __restrict__ lnb){
  int t0 = blockIdx.x*16, b = blockIdx.y;
  __shared__ __align__(16) float In[24][Hc];
  __shared__ __align__(16) float Outp[16][Hc];
  __shared__ float Wd[Hc*KERc];
  __shared__ float Bd[Hc], Lw[Hc], Lb[Hc];
  int tid = threadIdx.x;
  if(blockIdx.x==0){
    for(int e=tid; e<HIDc; e+=256) g_gxsq[b*HIDc+e] = 0.f;
  }
  for(int e=tid; e<24*48; e+=256){
    int i = e/48, q = e%48;
    int tg = t0 - 4 + i;
    tg = tg < 0 ? 0 : (tg > Qc-1 ? Qc-1 : tg);
    *(float4*)&In[i][q*4] = *(const float4*)&g_h[((size_t)b*Qc + tg)*Hc + q*4];
  }
  for(int e=tid; e<Hc*KERc; e+=256) Wd[e] = dww[e];
  for(int e=tid; e<Hc; e+=256){ Bd[e] = dwb[e]; Lw[e] = lnw[e]; Lb[e] = lnb[e]; }
  __syncthreads();
  for(int e=tid; e<16*Hc; e+=256){
    int t = e/Hc, c = e%Hc;
    float acc = Bd[c];
#pragma unroll
    for(int k=0;k<KERc;k++) acc += In[t+k][c]*Wd[c*KERc+k];
    Outp[t][c] = acc;
  }
  __syncthreads();
  int w = tid>>5, lane = tid&31;
  for(int rep=0; rep<2; rep++){
    int t = w + rep*8;
    float v[6]; float s = 0.f;
#pragma unroll
    for(int j=0;j<6;j++){ v[j] = Outp[t][lane+32*j]; s += v[j]; }
    s = wred(s);
    float m = s*(1.f/192.f);
    float sq = 0.f;
#pragma unroll
    for(int j=0;j<6;j++){ float d = v[j]-m; sq += d*d; }
    sq = wred(sq);
    float rstd = rsqrtf(sq*(1.f/192.f) + 1e-5f);
#pragma unroll
    for(int j=0;j<6;j++){
      int c = lane+32*j;
      Outp[t][c] = (v[j]-m)*rstd*Lw[c] + Lb[c];
    }
  }
  __syncthreads();
  for(int e=tid; e<16*48; e+=256){
    int t = e/48, q = e%48;
    *(float4*)&g_af[((size_t)b*Qc + t0 + t)*Hc + q*4] = *(float4*)&Outp[t][q*4];
  }
}

// ============ 3) pw1: f32x2 GEMM (M=128 t, N=64 o, K=192) + bias + GELU + fused gx ============
__global__ void __launch_bounds__(128,4) k_pw1x(const float* __restrict__ W,
                                                const float* __restrict__ bias){
  __shared__ __align__(16) float As[32][132];
  __shared__ __align__(16) float Ws[32][68];
  __shared__ float osq[64];
  int t0 = blockIdx.x*128, o0 = blockIdx.y*64, b = blockIdx.z;
  int tid = threadIdx.x, tx = tid&15, ty = tid>>4;  // ty 0..7
  if(tid<64) osq[tid] = 0.f;
  unsigned long long acc[4][8] = {};
  const float* Ag = g_af + ((size_t)b*Qc + t0)*Hc;
  for(int c0=0;c0<Hc;c0+=32){
    __syncthreads();
    for(int e=tid;e<1024;e+=128){
      int kq=e&7, t=e>>3;
      float4 v = *(const float4*)&Ag[(size_t)t*Hc + c0 + kq*4];
      As[kq*4+0][t]=v.x; As[kq*4+1][t]=v.y; As[kq*4+2][t]=v.z; As[kq*4+3][t]=v.w;
    }
    for(int e=tid;e<512;e+=128){
      int o=e>>3, kq=e&7;
      float4 w = *(const float4*)&W[(size_t)(o0+o)*Hc + c0 + kq*4];
      Ws[kq*4+0][o]=w.x; Ws[kq*4+1][o]=w.y; Ws[kq*4+2][o]=w.z; Ws[kq*4+3][o]=w.w;
    }
    __syncthreads();
#pragma unroll 8
    for(int k=0;k<32;k++){
      ulonglong2 wv = *(const ulonglong2*)&Ws[k][tx*4];
#pragma unroll
      for(int j=0;j<8;j++){
        unsigned long long ad0 = dupf(As[k][ty*8+j]);
        unsigned long long ad1 = dupf(As[k][64+ty*8+j]);
        ffma2(acc[0][j], wv.x, ad0);
        ffma2(acc[1][j], wv.y, ad0);
        ffma2(acc[2][j], wv.x, ad1);
        ffma2(acc[3][j], wv.y, ad1);
      }
    }
  }
  float4 bo = *(const float4*)&bias[o0 + tx*4];
  float sq[4] = {};
#pragma unroll
  for(int g=0;g<2;g++){
#pragma unroll
    for(int j=0;j<8;j++){
      int t = t0 + g*64 + ty*8 + j;
      float2 p0 = unpk(acc[2*g][j]);
      float2 p1 = unpk(acc[2*g+1][j]);
      float4 v;
      v.x = gelu_exact(p0.x + bo.x);
      v.y = gelu_exact(p0.y + bo.y);
      v.z = gelu_exact(p1.x + bo.z);
      v.w = gelu_exact(p1.y + bo.w);
      sq[0]+=v.x*v.x; sq[1]+=v.y*v.y; sq[2]+=v.z*v.z; sq[3]+=v.w*v.w;
      *(float4*)&g_midf[((size_t)b*Qc + t)*HIDc + o0 + tx*4] = v;
    }
  }
  atomicAdd(&osq[tx*4+0], sq[0]);
  atomicAdd(&osq[tx*4+1], sq[1]);
  atomicAdd(&osq[tx*4+2], sq[2]);
  atomicAdd(&osq[tx*4+3], sq[3]);
  __syncthreads();
  if(tid<64) atomicAdd(&g_gxsq[b*HIDc + o0 + tid], osq[tid]);
}

// ============ 5) pw2: f32x2 GEMM (M=128 t, N=64 o, K=384); GRN scale computed in-CTA ============
__global__ void __launch_bounds__(128,4) k_pw2x(const float* __restrict__ W,
                                                const float* __restrict__ bias,
                                                const float* __restrict__ grnb,
                                                const float* __restrict__ gg){
  __shared__ __align__(16) float As[32][132];
  __shared__ __align__(16) float Ws[32][68];
  __shared__ float sc_s[HIDc], gb_s[HIDc];
  __shared__ float sred[4];
  int t0 = blockIdx.x*128, o0 = blockIdx.y*64, b = blockIdx.z;
  int tid = threadIdx.x, tx = tid&15, ty = tid>>4;
  // ---- fused GRN scale (redundant per CTA, deterministic) ----
  {
    int wid = tid>>5, lane = tid&31;
    float v3[3]; float psum = 0.f;
#pragma unroll
    for(int i=0;i<3;i++){
      float vv = sqrtf(g_gxsq[b*HIDc + tid*3 + i]);
      v3[i] = vv; psum += vv;
    }
    psum = wred(psum);
    if(lane==0) sred[wid] = psum;
    __syncthreads();
    float mean = (sred[0]+sred[1]+sred[2]+sred[3])*(1.f/384.f);
#pragma unroll
    for(int i=0;i<3;i++){
      int o = tid*3 + i;
      sc_s[o] = 1.f + gg[o]*v3[i]/(mean + 1e-6f);
      gb_s[o] = grnb[o];
    }
  }
  unsigned long long acc[4][8] = {};
  const float* Ag = g_midf + ((size_t)b*Qc + t0)*HIDc;
  for(int c0=0;c0<HIDc;c0+=32){
    __syncthreads();
    for(int e=tid;e<1024;e+=128){
      int kq=e&7, t=e>>3;
      int c = c0 + kq*4;
      float4 m = *(const float4*)&Ag[(size_t)t*HIDc + c];
      As[kq*4+0][t] = m.x*sc_s[c+0] + gb_s[c+0];
      As[kq*4+1][t] = m.y*sc_s[c+1] + gb_s[c+1];
      As[kq*4+2][t] = m.z*sc_s[c+2] + gb_s[c+2];
      As[kq*4+3][t] = m.w*sc_s[c+3] + gb_s[c+3];
    }
    for(int e=tid;e<512;e+=128){
      int o=e>>3, kq=e&7;
      float4 w = *(const float4*)&W[(size_t)(o0+o)*HIDc + c0 + kq*4];
      Ws[kq*4+0][o]=w.x; Ws[kq*4+1][o]=w.y; Ws[kq*4+2][o]=w.z; Ws[kq*4+3][o]=w.w;
    }
    __syncthreads();
#pragma unroll 8
    for(int k=0;k<32;k++){
      ulonglong2 wv = *(const ulonglong2*)&Ws[k][tx*4];
#pragma unroll
      for(int j=0;j<8;j++){
        unsigned long long ad0 = dupf(As[k][ty*8+j]);
        unsigned long long ad1 = dupf(As[k][64+ty*8+j]);
        ffma2(acc[0][j], wv.x, ad0);
        ffma2(acc[1][j], wv.y, ad0);
        ffma2(acc[2][j], wv.x, ad1);
        ffma2(acc[3][j], wv.y, ad1);
      }
    }
  }
  float4 bo = *(const float4*)&bias[o0 + tx*4];
#pragma unroll
  for(int g=0;g<2;g++){
#pragma unroll
    for(int j=0;j<8;j++){
      int t = t0 + g*64 + ty*8 + j;
      float* hrow = g_h + ((size_t)b*Qc + t)*Hc + o0 + tx*4;
      float4 h = *(float4*)hrow;
      float2 p0 = unpk(acc[2*g][j]);
      float2 p1 = unpk(acc[2*g+1][j]);
      h.x += p0.x + bo.x;
      h.y += p0.y + bo.y;
      h.z += p1.x + bo.z;
      h.w += p1.y + bo.w;
      *(float4*)hrow = h;
    }
  }
}

// ============ 7) Kalman precompute with fused output-LN ============
__global__ void __launch_bounds__(256) k_scanprep(const float* __restrict__ olnw,
                                                  const float* __restrict__ olnb,
                                                  const float* __restrict__ rpw,
                                                  const float* __restrict__ rpb,
                                                  const float* __restrict__ gw,
                                                  const float* __restrict__ gb){
  int t0 = blockIdx.x*16, b = blockIdx.y;
  __shared__ float Hs[16][193];
  __shared__ float Ws[34][193];
  __shared__ float bs[34];
  __shared__ float outs[16][34];
  int tid = threadIdx.x;
  for(int e=tid; e<16*Hc; e+=256){
    int t = e/Hc, h = e%Hc;
    Hs[t][h] = g_h[((size_t)b*Qc + t0 + t)*Hc + h];
  }
  for(int e=tid; e<34*Hc; e+=256){
    int j = e/Hc, h = e%Hc;
    Ws[j][h] = (j<2) ? rpw[j*Hc + h] : gw[(j-2)*Hc + h];
  }
  if(tid<34) bs[tid] = (tid<2) ? rpb[tid] : gb[tid-2];
  __syncthreads();
  // fused output LN (identical reduction order to the old k_outln)
  {
    int w = tid>>5, lane = tid&31;
    for(int rep=0; rep<2; rep++){
      int t = w + rep*8;
      float v[6]; float s = 0.f;
#pragma unroll
      for(int j=0;j<6;j++){ v[j] = Hs[t][lane+32*j]; s += v[j]; }
      s = wred(s);
      float m = s*(1.f/192.f);
      float sq = 0.f;
#pragma unroll
      for(int j=0;j<6;j++){ float d = v[j]-m; sq += d*d; }
      sq = wred(sq);
      float rstd = rsqrtf(sq*(1.f/192.f) + 1e-5f);
#pragma unroll
      for(int j=0;j<6;j++){
        int c = lane+32*j;
        Hs[t][c] = (v[j]-m)*rstd*olnw[c] + olnb[c];
      }
    }
  }
  __syncthreads();
  if(t0 == Qc-16){
    for(int e=tid; e<Hc; e+=256)
      g_hseq[((size_t)b*Qc + (Qc-1))*Hc + e] = Hs[15][e];
  }
  for(int e=tid; e<16*34; e+=256){
    int t = e/34, j = e%34;
    float acc = bs[j];
    for(int h=0;h<Hc;h++) acc += Hs[t][h]*Ws[j][h];
    float v;
    if(j==0)      v = 1.25f*sigm(acc);
    else if(j==1) v = PI_F*tanhf(acc);
    else          v = sigm(acc);
    outs[t][j] = v;
  }
  __syncthreads();
  if(tid<16){
    float rho = outs[tid][0], phi = outs[tid][1];
    float sn, cs; sincosf(phi, &sn, &cs);
    outs[tid][0] = rho*cs;
    outs[tid][1] = rho*sn;
  }
  __syncthreads();
  for(int e=tid; e<16*34; e+=256){
    int t = e/34, j = e%34;
    g_rpg[((size_t)b*Qc + t0 + t)*34 + j] = outs[t][j];
  }
}

// ============ 8) sequential Kalman scan + fused rollout init ============
__global__ void k_scan(const float* __restrict__ x){
  int b = blockIdx.x, d = threadIdx.x;
  const float* xb = x + (size_t)b*Qc*Dc;
  const float* rp = g_rpg + (size_t)b*Qc*34;
  float xp = xb[d];
  float sign = (d<16) ? -1.f : 1.f;
  float rc = rp[0], rs = rp[1], gn = rp[2+d], y = xb[d];
  for(int t=0;t<Qc;t++){
    float nrc=0.f, nrs=0.f, ngn=0.f, ny=0.f;
    if(t+1<Qc){
      const float* r = rp + (size_t)(t+1)*34;
      nrc = r[0]; nrs = r[1]; ngn = r[2+d];
      ny = xb[(size_t)(t+1)*Dc + d];
    }
    float other = __shfl_xor_sync(0xffffffffu, xp, 16);
    float xpri = rc*xp + sign*rs*other;
    xp = xpri + gn*(y - xpri);
    rc=nrc; rs=nrs; gn=ngn; y=ny;
  }
  g_curr[b*Dc + d] = xp;
  for(int h=d; h<Hc; h+=32)
    g_hr[b*Hc + h] = g_hseq[((size_t)b*Qc + (Qc-1))*Hc + h];
  if(b==0 && d==0){ g_cnt = 0u; g_gen = 0u; }
}

__device__ __forceinline__ void gridbar(unsigned NB){
  __threadfence();
  __syncthreads();
  if(threadIdx.x==0){
    unsigned gen = g_gen;
    if(atomicAdd(&g_cnt, 1u) == NB-1u){
      g_cnt = 0u;
      __threadfence();
      g_gen = gen + 1u;
    } else {
      while(g_gen == gen) __nanosleep(64);
    }
    __threadfence();
  }
  __syncthreads();
}

// ============ 10) persistent rollout ============
__global__ void __launch_bounds__(256) k_roll(const float* __restrict__ riW,
                                              const float* __restrict__ riB,
                                              const float* __restrict__ whh,
                                              const float* __restrict__ bhh,
                                              const float* __restrict__ wih,
                                              const float* __restrict__ bih,
                                              const float* __restrict__ lnw,
                                              const float* __restrict__ lnb,
                                              const float* __restrict__ rpw,
                                              const float* __restrict__ rpb,
                                              float* __restrict__ dout){
  __shared__ float In[32][33];
  __shared__ __align__(16) float Wt[32][68];
  __shared__ float red[12];
  __shared__ float curs[Dc];
  int tid = threadIdx.x;
  unsigned NB = gridDim.x;
  for(int step=0; step<WOUTc; step++){
    {
      int u = blockIdx.x;
      if(u < 96){
        int ox = u%12, by = u/12;
        bool xpath = ox<3;
        int o0 = xpath? ox*64 : (ox-3)*64;
        int b0 = by*32;
        int K  = xpath? (Hc+Dc) : Hc;
        const float* W = xpath? riW : whh;
        int tb = tid&15, to = tid>>4;
        float acc[2][4] = {};
        int nch = K/32;
        for(int ch=0; ch<nch; ch++){
          int c0 = ch*32;
          __syncthreads();
          for(int e=tid; e<1024; e+=256){
            int bb = e>>5, k = e&31;
            float v;
            if(xpath && ch==6) v = __ldcg(&g_curr[(b0+bb)*Dc + k]);
            else               v = __ldcg(&g_hr[(b0+bb)*Hc + c0 + k]);
            In[k][bb] = v;
          }
          for(int e=tid; e<2048; e+=256){
            int o = e>>5, k = e&31;
            Wt[k][o] = W[(size_t)(o0+o)*K + c0 + k];
          }
          __syncthreads();
#pragma unroll
          for(int k=0;k<32;k++){
            float a0 = In[k][tb*2], a1 = In[k][tb*2+1];
            float4 w = *(const float4*)&Wt[k][to<<2];
            acc[0][0]+=a0*w.x; acc[0][1]+=a0*w.y; acc[0][2]+=a0*w.z; acc[0][3]+=a0*w.w;
            acc[1][0]+=a1*w.x; acc[1][1]+=a1*w.y; acc[1][2]+=a1*w.z; acc[1][3]+=a1*w.w;
          }
        }
#pragma unroll
        for(int i=0;i<2;i++){
          int b = b0 + tb*2 + i;
#pragma unroll
          for(int j=0;j<4;j++){
            int o = o0 + (to<<2) + j;
            float v = acc[i][j];
            if(xpath) __stcg(&g_xr[b*Hc + o], tanhf(v + riB[o]));
            else      __stcg(&g_gh[b*3*Hc + o], v + bhh[o]);
          }
        }
      }
    }
    gridbar(NB);
    {
      int u = blockIdx.x;
      if(u < 72){
        int o0 = (u%9)*64, b0 = (u/9)*32;
        int tb = tid&15, to = tid>>4;
        float acc[2][4] = {};
        for(int ch=0; ch<6; ch++){
          int c0 = ch*32;
          __syncthreads();
          for(int e=tid; e<1024; e+=256){
            int bb = e>>5, k = e&31;
            In[k][bb] = __ldcg(&g_xr[(b0+bb)*Hc + c0 + k]);
          }
          for(int e=tid; e<2048; e+=256){
            int o = e>>5, k = e&31;
            Wt[k][o] = wih[(size_t)(o0+o)*Hc + c0 + k];
          }
          __syncthreads();
#pragma unroll
          for(int k=0;k<32;k++){
            float a0 = In[k][tb*2], a1 = In[k][tb*2+1];
            float4 w = *(const float4*)&Wt[k][to<<2];
            acc[0][0]+=a0*w.x; acc[0][1]+=a0*w.y; acc[0][2]+=a0*w.z; acc[0][3]+=a0*w.w;
            acc[1][0]+=a1*w.x; acc[1][1]+=a1*w.y; acc[1][2]+=a1*w.z; acc[1][3]+=a1*w.w;
          }
        }
#pragma unroll
        for(int i=0;i<2;i++){
          int b = b0 + tb*2 + i;
#pragma unroll
          for(int j=0;j<4;j++){
            int o = o0 + (to<<2) + j;
            __stcg(&g_gi[b*3*Hc + o], acc[i][j] + bih[o]);
          }
        }
      }
    }
    gridbar(NB);
    for(int rep=0; rep<2; rep++){
      int b = blockIdx.x + rep*128;
      int o = tid;
      bool act = o < Hc;
      int w = o>>5, lane = o&31;
      float v = 0.f, hr = 0.f;
      if(act){
        float gi0 = __ldcg(&g_gi[b*576 + o]),       gh0 = __ldcg(&g_gh[b*576 + o]);
        float gi1 = __ldcg(&g_gi[b*576 + 192 + o]), gh1 = __ldcg(&g_gh[b*576 + 192 + o]);
        float gi2 = __ldcg(&g_gi[b*576 + 384 + o]), gh2 = __ldcg(&g_gh[b*576 + 384 + o]);
        hr = __ldcg(&g_hr[b*Hc + o]);
        float r = sigm(gi0 + gh0);
        float z = sigm(gi1 + gh1);
        float n = tanhf(gi2 + r*gh2);
        v = (1.f - z)*n + z*hr;
      }
      if(o<Dc) curs[o] = __ldcg(&g_curr[b*Dc + o]);
      float s = wred(act? v : 0.f);
      if(lane==0 && w<6) red[w] = s;
      __syncthreads();
      float m = (red[0]+red[1]+red[2]+red[3]+red[4]+red[5])*(1.f/192.f);
      __syncthreads();
      float d0 = act? (v - m) : 0.f;
      s = wred(d0*d0);
      if(lane==0 && w<6) red[w] = s;
      __syncthreads();
      float var = (red[0]+red[1]+red[2]+red[3]+red[4]+red[5])*(1.f/192.f);
      float hn = 0.f;
      if(act){
        hn = d0*rsqrtf(var + 1e-5f)*lnw[o] + lnb[o];
        __stcg(&g_hr[b*Hc + o], hn);
      }
      __syncthreads();
      float s0 = wred(act? hn*rpw[o] : 0.f);
      float s1 = wred(act? hn*rpw[Hc + o] : 0.f);
      if(lane==0 && w<6){ red[w] = s0; red[6+w] = s1; }
      __syncthreads();
      float p0 = red[0]+red[1]+red[2]+red[3]+red[4]+red[5] + rpb[0];
      float p1 = red[6]+red[7]+red[8]+red[9]+red[10]+red[11] + rpb[1];
      float rho = 1.25f*sigm(p0);
      float phi = PI_F*tanhf(p1);
      float sn, cs; sincosf(phi, &sn, &cs);
      float rc = rho*cs, rs = rho*sn;
      if(o<Dc){
        float self = curs[o];
        float other = curs[o^16];
        float outv = rc*self + ((o<16)? -rs : rs)*other;
        __stcg(&g_curr[b*Dc + o], outv);
        dout[((size_t)b*WOUTc + step)*Dc + o] = outv;
      }
      __syncthreads();
    }
    gridbar(NB);
  }
}

// ============================== launch ==============================
extern "C" void kernel_launch(void* const* d_in, const int* in_sizes, int n_in,
                              void* d_out, int out_size){
  const float* x_in    = (const float*)d_in[0];
  const float* inp_w   = (const float*)d_in[1];
  const float* inp_b   = (const float*)d_in[2];
  const float* b_dw_w  = (const float*)d_in[3];
  const float* b_dw_b  = (const float*)d_in[4];
  const float* b_ln_w  = (const float*)d_in[5];
  const float* b_ln_b  = (const float*)d_in[6];
  const float* b_pw1_w = (const float*)d_in[7];
  const float* b_pw1_b = (const float*)d_in[8];
  const float* b_grn_g = (const float*)d_in[9];
  const float* b_grn_b = (const float*)d_in[10];
  const float* b_pw2_w = (const float*)d_in[11];
  const float* b_pw2_b = (const float*)d_in[12];
  const float* out_ln_w= (const float*)d_in[13];
  const float* out_ln_b= (const float*)d_in[14];
  const float* fc_rp_w = (const float*)d_in[15];
  const float* fc_rp_b = (const float*)d_in[16];
  const float* fc_gain_w=(const float*)d_in[17];
  const float* fc_gain_b=(const float*)d_in[18];
  const float* roll_in_w=(const float*)d_in[19];
  const float* roll_in_b=(const float*)d_in[20];
  const float* gru_wih = (const float*)d_in[21];
  const float* gru_whh = (const float*)d_in[22];
  const float* gru_bih = (const float*)d_in[23];
  const float* gru_bhh = (const float*)d_in[24];
  const float* roll_ln_w=(const float*)d_in[25];
  const float* roll_ln_b=(const float*)d_in[26];
  const float* fc_rp_r_w=(const float*)d_in[27];
  const float* fc_rp_r_b=(const float*)d_in[28];
  float* dout = (float*)d_out;

  k_featproj<<<dim3(Qc/64, Hc/64, Bc), 256>>>(x_in, inp_w, inp_b);

  for(int i=0;i<2;i++){
    k_dwconv_ln<<<dim3(Qc/16, Bc), 256>>>(b_dw_w + (size_t)i*Hc*KERc,
                                          b_dw_b + (size_t)i*Hc,
                                          b_ln_w + (size_t)i*Hc,
                                          b_ln_b + (size_t)i*Hc);
    k_pw1x<<<dim3(Qc/128, HIDc/64, Bc), 128>>>(b_pw1_w + (size_t)i*HIDc*Hc,
                                               b_pw1_b + (size_t)i*HIDc);
    k_pw2x<<<dim3(Qc/128, Hc/64, Bc), 128>>>(b_pw2_w + (size_t)i*Hc*HIDc,
                                             b_pw2_b + (size_t)i*Hc,
                                             b_grn_b + (size_t)i*HIDc,
                                             b_grn_g + (size_t)i*HIDc);
  }

  k_scanprep<<<dim3(Qc/16, Bc), 256>>>(out_ln_w, out_ln_b,
                                       fc_rp_w, fc_rp_b, fc_gain_w, fc_gain_b);
  k_scan<<<Bc, 32>>>(x_in);

  k_roll<<<128, 256>>>(roll_in_w, roll_in_b, gru_whh, gru_bhh,
                       gru_wih, gru_bih, roll_ln_w, roll_ln_b,
                       fc_rp_r_w, fc_rp_r_b, dout);
}

// round 16
// speedup vs baseline: 1.0870x; 1.0075x over previous
#include <cuda_runtime.h>
#include <cuda_bf16.h>
#include <math.h>
#include <stdint.h>

#define Bc 256
#define Qc 512
#define Dc 32
#define Hc 192
#define HIDc 384
#define INCHc 96
#define KERc 9
#define WOUTc 64
#define PI_F 3.14159265358979f

// ---------------- scratch (all fp32 — trunk precision is load-bearing) ----------------
__device__ __align__(16) float g_h   [(size_t)Bc*Qc*Hc];    // residual (B,Q,H)
__device__ __align__(16) float g_af  [(size_t)Bc*Qc*Hc];    // LN'd act (B,Q,H)
__device__ __align__(16) float g_midf[(size_t)Bc*Qc*HIDc];  // pw1 out  (B,Q,HID)
__device__ __align__(16) float g_hseq[(size_t)Bc*Qc*Hc];    // only t=511 rows used
__device__ float g_gxsq[Bc*HIDc];
__device__ float g_rpg [(size_t)Bc*Qc*34];
__device__ float g_hr  [Bc*Hc];
__device__ float g_xr  [Bc*Hc];
__device__ float g_gi  [Bc*3*Hc];
__device__ float g_gh  [Bc*3*Hc];
__device__ float g_curr[Bc*Dc];
__device__ unsigned g_cnt;
__device__ volatile unsigned g_gen;

// ---------------- helpers ----------------
__device__ __forceinline__ float sigm(float x){ return 1.f/(1.f+expf(-x)); }
__device__ __forceinline__ float gelu_exact(float x){ return 0.5f*x*(1.f+erff(x*0.70710678118654752f)); }
__device__ __forceinline__ float wred(float v){
#pragma unroll
  for(int s=16;s;s>>=1) v += __shfl_xor_sync(0xffffffffu, v, s);
  return v;
}
__device__ __forceinline__ unsigned long long dupf(float w){
  unsigned long long r;
  asm("mov.b64 %0, {%1, %1};" : "=l"(r) : "f"(w));
  return r;
}
__device__ __forceinline__ void ffma2(unsigned long long &acc, unsigned long long a, unsigned long long b){
  asm("fma.rn.f32x2 %0, %1, %2, %0;" : "+l"(acc) : "l"(a), "l"(b));
}
__device__ __forceinline__ float2 unpk(unsigned long long p){
  float2 f; asm("mov.b64 {%0, %1}, %2;" : "=f"(f.x), "=f"(f.y) : "l"(p));
  return f;
}

// ============ 1) features + input projection -> g_h (B,Q,H) ============
__global__ void __launch_bounds__(256) k_featproj(const float* __restrict__ x,
                                                  const float* __restrict__ W,
                                                  const float* __restrict__ bias){
  int t0 = blockIdx.x*64, o0 = blockIdx.y*64, b = blockIdx.z;
  __shared__ __align__(16) float Xs[66][33];
  __shared__ __align__(16) float As[32][64];
  __shared__ __align__(16) float Ws[32][68];
  int tid = threadIdx.x;
  for(int e=tid; e<66*32; e+=256){
    int i = e>>5, d = e&31;
    int tg = t0 - 2 + i;
    float v = 0.f;
    if(tg>=0 && tg<Qc) v = x[((size_t)b*Qc + tg)*Dc + d];
    Xs[i][d] = v;
  }
  int tx = tid & 15, ty = tid >> 4;
  float acc[4][4] = {};
  for(int j=0;j<3;j++){
    __syncthreads();
    for(int e=tid; e<2048; e+=256){
      int k = e>>6, t = e&63;
      int tg = t0+t;
      float x0 = Xs[t+2][k], x1 = Xs[t+1][k], x2 = Xs[t][k];
      float v;
      if(j==0)      v = x0;
      else if(j==1) v = (tg>=1)? x0-x1 : 0.f;
      else          v = (tg>=2)? (x0-2.f*x1+x2) : ((tg==1)? x0-x1 : 0.f);
      As[k][t] = v;
    }
    for(int e=tid; e<2048; e+=256){
      int o = e>>5, k = e&31;
      Ws[k][o] = W[(size_t)(o0+o)*INCHc + j*32 + k];
    }
    __syncthreads();
#pragma unroll
    for(int k=0;k<32;k++){
      float4 a = *(const float4*)&As[k][tx<<2];
      float4 w = *(const float4*)&Ws[k][ty<<2];
      acc[0][0]+=w.x*a.x; acc[0][1]+=w.x*a.y; acc[0][2]+=w.x*a.z; acc[0][3]+=w.x*a.w;
      acc[1][0]+=w.y*a.x; acc[1][1]+=w.y*a.y; acc[1][2]+=w.y*a.z; acc[1][3]+=w.y*a.w;
      acc[2][0]+=w.z*a.x; acc[2][1]+=w.z*a.y; acc[2][2]+=w.z*a.z; acc[2][3]+=w.z*a.w;
      acc[3][0]+=w.w*a.x; acc[3][1]+=w.w*a.y; acc[3][2]+=w.w*a.z; acc[3][3]+=w.w*a.w;
    }
  }
  float4 bo = *(const float4*)&bias[o0 + (ty<<2)];
#pragma unroll
  for(int jj=0;jj<4;jj++){
    int t = t0 + (tx<<2) + jj;
    float4 v;
    v.x = acc[0][jj] + bo.x;
    v.y = acc[1][jj] + bo.y;
    v.z = acc[2][jj] + bo.z;
    v.w = acc[3][jj] + bo.w;
    *(float4*)&g_h[((size_t)b*Qc + t)*Hc + o0 + (ty<<2)] = v;
  }
}

// ============ 2) dwconv (k=9 edge pad) + LN -> g_af fp32 (B,Q,H); zero gxsq ============
__global__ void __launch_bounds__(256) k_dwconv_ln(const float* __restrict__ dww,
                                                   const float* __restrict__ dwb,
                                                   const float* __restrict__ lnw,
                                                   const float* __restrict__ lnb){
  int t0 = blockIdx.x*16, b = blockIdx.y;
  __shared__ __align__(16) float In[24][Hc];
  __shared__ __align__(16) float Outp[16][Hc];
  __shared__ float Wd[Hc*KERc];
  __shared__ float Bd[Hc], Lw[Hc], Lb[Hc];
  int tid = threadIdx.x;
  if(blockIdx.x==0){
    for(int e=tid; e<HIDc; e+=256) g_gxsq[b*HIDc+e] = 0.f;
  }
  for(int e=tid; e<24*48; e+=256){
    int i = e/48, q = e%48;
    int tg = t0 - 4 + i;
    tg = tg < 0 ? 0 : (tg > Qc-1 ? Qc-1 : tg);
    *(float4*)&In[i][q*4] = *(const float4*)&g_h[((size_t)b*Qc + tg)*Hc + q*4];
  }
  for(int e=tid; e<Hc*KERc; e+=256) Wd[e] = dww[e];
  for(int e=tid; e<Hc; e+=256){ Bd[e] = dwb[e]; Lw[e] = lnw[e]; Lb[e] = lnb[e]; }
  __syncthreads();
  for(int e=tid; e<16*Hc; e+=256){
    int t = e/Hc, c = e%Hc;
    float acc = Bd[c];
#pragma unroll
    for(int k=0;k<KERc;k++) acc += In[t+k][c]*Wd[c*KERc+k];
    Outp[t][c] = acc;
  }
  __syncthreads();
  int w = tid>>5, lane = tid&31;
  for(int rep=0; rep<2; rep++){
    int t = w + rep*8;
    float v[6]; float s = 0.f;
#pragma unroll
    for(int j=0;j<6;j++){ v[j] = Outp[t][lane+32*j]; s += v[j]; }
    s = wred(s);
    float m = s*(1.f/192.f);
    float sq = 0.f;
#pragma unroll
    for(int j=0;j<6;j++){ float d = v[j]-m; sq += d*d; }
    sq = wred(sq);
    float rstd = rsqrtf(sq*(1.f/192.f) + 1e-5f);
#pragma unroll
    for(int j=0;j<6;j++){
      int c = lane+32*j;
      Outp[t][c] = (v[j]-m)*rstd*Lw[c] + Lb[c];
    }
  }
  __syncthreads();
  for(int e=tid; e<16*48; e+=256){
    int t = e/48, q = e%48;
    *(float4*)&g_af[((size_t)b*Qc + t0 + t)*Hc + q*4] = *(float4*)&Outp[t][q*4];
  }
}

// ============ 3) pw1: f32x2 GEMM (128t x 64o, K=192), t-pairs packed; + bias + GELU + fused gx ============
__global__ void __launch_bounds__(128,4) k_pw1x(const float* __restrict__ W,
                                                const float* __restrict__ bias){
  __shared__ __align__(16) float As[32][132];
  __shared__ __align__(16) float Ws[32][68];
  __shared__ float osq[64];
  int t0 = blockIdx.x*128, o0 = blockIdx.y*64, b = blockIdx.z;
  int tid = threadIdx.x, tx = tid&15, ty = tid>>4;  // ty 0..7
  if(tid<64) osq[tid] = 0.f;
  unsigned long long acc[4][8] = {};   // [o][t-pair: 0..3 grp0, 4..7 grp1]
  const float* Ag = g_af + ((size_t)b*Qc + t0)*Hc;
  for(int c0=0;c0<Hc;c0+=32){
    __syncthreads();
    for(int e=tid;e<1024;e+=128){
      int kq=e&7, t=e>>3;
      float4 v = *(const float4*)&Ag[(size_t)t*Hc + c0 + kq*4];
      As[kq*4+0][t]=v.x; As[kq*4+1][t]=v.y; As[kq*4+2][t]=v.z; As[kq*4+3][t]=v.w;
    }
    for(int e=tid;e<512;e+=128){
      int o=e>>3, kq=e&7;
      float4 w = *(const float4*)&W[(size_t)(o0+o)*Hc + c0 + kq*4];
      Ws[kq*4+0][o]=w.x; Ws[kq*4+1][o]=w.y; Ws[kq*4+2][o]=w.z; Ws[kq*4+3][o]=w.w;
    }
    __syncthreads();
#pragma unroll 8
    for(int k=0;k<32;k++){
      ulonglong2 a01 = *(const ulonglong2*)&As[k][ty*8];
      ulonglong2 a23 = *(const ulonglong2*)&As[k][ty*8+4];
      ulonglong2 b01 = *(const ulonglong2*)&As[k][64+ty*8];
      ulonglong2 b23 = *(const ulonglong2*)&As[k][64+ty*8+4];
      float4 w = *(const float4*)&Ws[k][tx*4];
      unsigned long long w0=dupf(w.x), w1=dupf(w.y), w2=dupf(w.z), w3=dupf(w.w);
      ffma2(acc[0][0], w0, a01.x); ffma2(acc[0][1], w0, a01.y);
      ffma2(acc[0][2], w0, a23.x); ffma2(acc[0][3], w0, a23.y);
      ffma2(acc[0][4], w0, b01.x); ffma2(acc[0][5], w0, b01.y);
      ffma2(acc[0][6], w0, b23.x); ffma2(acc[0][7], w0, b23.y);
      ffma2(acc[1][0], w1, a01.x); ffma2(acc[1][1], w1, a01.y);
      ffma2(acc[1][2], w1, a23.x); ffma2(acc[1][3], w1, a23.y);
      ffma2(acc[1][4], w1, b01.x); ffma2(acc[1][5], w1, b01.y);
      ffma2(acc[1][6], w1, b23.x); ffma2(acc[1][7], w1, b23.y);
      ffma2(acc[2][0], w2, a01.x); ffma2(acc[2][1], w2, a01.y);
      ffma2(acc[2][2], w2, a23.x); ffma2(acc[2][3], w2, a23.y);
      ffma2(acc[2][4], w2, b01.x); ffma2(acc[2][5], w2, b01.y);
      ffma2(acc[2][6], w2, b23.x); ffma2(acc[2][7], w2, b23.y);
      ffma2(acc[3][0], w3, a01.x); ffma2(acc[3][1], w3, a01.y);
      ffma2(acc[3][2], w3, a23.x); ffma2(acc[3][3], w3, a23.y);
      ffma2(acc[3][4], w3, b01.x); ffma2(acc[3][5], w3, b01.y);
      ffma2(acc[3][6], w3, b23.x); ffma2(acc[3][7], w3, b23.y);
    }
  }
  float4 bo = *(const float4*)&bias[o0 + tx*4];
  float sq[4] = {};
#pragma unroll
  for(int g=0;g<2;g++){
#pragma unroll
    for(int j=0;j<8;j++){
      int t = t0 + g*64 + ty*8 + j;
      int tp = g*4 + (j>>1);
      float2 p0 = unpk(acc[0][tp]);
      float2 p1 = unpk(acc[1][tp]);
      float2 p2 = unpk(acc[2][tp]);
      float2 p3 = unpk(acc[3][tp]);
      float4 v;
      v.x = gelu_exact(((j&1)? p0.y : p0.x) + bo.x);
      v.y = gelu_exact(((j&1)? p1.y : p1.x) + bo.y);
      v.z = gelu_exact(((j&1)? p2.y : p2.x) + bo.z);
      v.w = gelu_exact(((j&1)? p3.y : p3.x) + bo.w);
      sq[0]+=v.x*v.x; sq[1]+=v.y*v.y; sq[2]+=v.z*v.z; sq[3]+=v.w*v.w;
      *(float4*)&g_midf[((size_t)b*Qc + t)*HIDc + o0 + tx*4] = v;
    }
  }
  atomicAdd(&osq[tx*4+0], sq[0]);
  atomicAdd(&osq[tx*4+1], sq[1]);
  atomicAdd(&osq[tx*4+2], sq[2]);
  atomicAdd(&osq[tx*4+3], sq[3]);
  __syncthreads();
  if(tid<64) atomicAdd(&g_gxsq[b*HIDc + o0 + tid], osq[tid]);
}

// ============ 5) pw2: f32x2 GEMM (128t x 64o, K=384), t-pairs packed; GRN in-CTA + residual ============
__global__ void __launch_bounds__(128,4) k_pw2x(const float* __restrict__ W,
                                                const float* __restrict__ bias,
                                                const float* __restrict__ grnb,
                                                const float* __restrict__ gg){
  __shared__ __align__(16) float As[32][132];
  __shared__ __align__(16) float Ws[32][68];
  __shared__ float sc_s[HIDc], gb_s[HIDc];
  __shared__ float sred[4];
  int t0 = blockIdx.x*128, o0 = blockIdx.y*64, b = blockIdx.z;
  int tid = threadIdx.x, tx = tid&15, ty = tid>>4;
  // ---- fused GRN scale (redundant per CTA, deterministic) ----
  {
    int wid = tid>>5, lane = tid&31;
    float v3[3]; float psum = 0.f;
#pragma unroll
    for(int i=0;i<3;i++){
      float vv = sqrtf(g_gxsq[b*HIDc + tid*3 + i]);
      v3[i] = vv; psum += vv;
    }
    psum = wred(psum);
    if(lane==0) sred[wid] = psum;
    __syncthreads();
    float mean = (sred[0]+sred[1]+sred[2]+sred[3])*(1.f/384.f);
#pragma unroll
    for(int i=0;i<3;i++){
      int o = tid*3 + i;
      sc_s[o] = 1.f + gg[o]*v3[i]/(mean + 1e-6f);
      gb_s[o] = grnb[o];
    }
  }
  unsigned long long acc[4][8] = {};
  const float* Ag = g_midf + ((size_t)b*Qc + t0)*HIDc;
  for(int c0=0;c0<HIDc;c0+=32){
    __syncthreads();
    for(int e=tid;e<1024;e+=128){
      int kq=e&7, t=e>>3;
      int c = c0 + kq*4;
      float4 m = *(const float4*)&Ag[(size_t)t*HIDc + c];
      As[kq*4+0][t] = m.x*sc_s[c+0] + gb_s[c+0];
      As[kq*4+1][t] = m.y*sc_s[c+1] + gb_s[c+1];
      As[kq*4+2][t] = m.z*sc_s[c+2] + gb_s[c+2];
      As[kq*4+3][t] = m.w*sc_s[c+3] + gb_s[c+3];
    }
    for(int e=tid;e<512;e+=128){
      int o=e>>3, kq=e&7;
      float4 w = *(const float4*)&W[(size_t)(o0+o)*HIDc + c0 + kq*4];
      Ws[kq*4+0][o]=w.x; Ws[kq*4+1][o]=w.y; Ws[kq*4+2][o]=w.z; Ws[kq*4+3][o]=w.w;
    }
    __syncthreads();
#pragma unroll 8
    for(int k=0;k<32;k++){
      ulonglong2 a01 = *(const ulonglong2*)&As[k][ty*8];
      ulonglong2 a23 = *(const ulonglong2*)&As[k][ty*8+4];
      ulonglong2 b01 = *(const ulonglong2*)&As[k][64+ty*8];
      ulonglong2 b23 = *(const ulonglong2*)&As[k][64+ty*8+4];
      float4 w = *(const float4*)&Ws[k][tx*4];
      unsigned long long w0=dupf(w.x), w1=dupf(w.y), w2=dupf(w.z), w3=dupf(w.w);
      ffma2(acc[0][0], w0, a01.x); ffma2(acc[0][1], w0, a01.y);
      ffma2(acc[0][2], w0, a23.x); ffma2(acc[0][3], w0, a23.y);
      ffma2(acc[0][4], w0, b01.x); ffma2(acc[0][5], w0, b01.y);
      ffma2(acc[0][6], w0, b23.x); ffma2(acc[0][7], w0, b23.y);
      ffma2(acc[1][0], w1, a01.x); ffma2(acc[1][1], w1, a01.y);
      ffma2(acc[1][2], w1, a23.x); ffma2(acc[1][3], w1, a23.y);
      ffma2(acc[1][4], w1, b01.x); ffma2(acc[1][5], w1, b01.y);
      ffma2(acc[1][6], w1, b23.x); ffma2(acc[1][7], w1, b23.y);
      ffma2(acc[2][0], w2, a01.x); ffma2(acc[2][1], w2, a01.y);
      ffma2(acc[2][2], w2, a23.x); ffma2(acc[2][3], w2, a23.y);
      ffma2(acc[2][4], w2, b01.x); ffma2(acc[2][5], w2, b01.y);
      ffma2(acc[2][6], w2, b23.x); ffma2(acc[2][7], w2, b23.y);
      ffma2(acc[3][0], w3, a01.x); ffma2(acc[3][1], w3, a01.y);
      ffma2(acc[3][2], w3, a23.x); ffma2(acc[3][3], w3, a23.y);
      ffma2(acc[3][4], w3, b01.x); ffma2(acc[3][5], w3, b01.y);
      ffma2(acc[3][6], w3, b23.x); ffma2(acc[3][7], w3, b23.y);
    }
  }
  float4 bo = *(const float4*)&bias[o0 + tx*4];
#pragma unroll
  for(int g=0;g<2;g++){
#pragma unroll
    for(int j=0;j<8;j++){
      int t = t0 + g*64 + ty*8 + j;
      int tp = g*4 + (j>>1);
      float* hrow = g_h + ((size_t)b*Qc + t)*Hc + o0 + tx*4;
      float4 h = *(float4*)hrow;
      float2 p0 = unpk(acc[0][tp]);
      float2 p1 = unpk(acc[1][tp]);
      float2 p2 = unpk(acc[2][tp]);
      float2 p3 = unpk(acc[3][tp]);
      h.x += ((j&1)? p0.y : p0.x) + bo.x;
      h.y += ((j&1)? p1.y : p1.x) + bo.y;
      h.z += ((j&1)? p2.y : p2.x) + bo.z;
      h.w += ((j&1)? p3.y : p3.x) + bo.w;
      *(float4*)hrow = h;
    }
  }
}

// ============ 7) Kalman precompute with fused output-LN ============
__global__ void __launch_bounds__(256) k_scanprep(const float* __restrict__ olnw,
                                                  const float* __restrict__ olnb,
                                                  const float* __restrict__ rpw,
                                                  const float* __restrict__ rpb,
                                                  const float* __restrict__ gw,
                                                  const float* __restrict__ gb){
  int t0 = blockIdx.x*16, b = blockIdx.y;
  __shared__ float Hs[16][193];
  __shared__ float Ws[34][193];
  __shared__ float bs[34];
  __shared__ float outs[16][34];
  int tid = threadIdx.x;
  for(int e=tid; e<16*Hc; e+=256){
    int t = e/Hc, h = e%Hc;
    Hs[t][h] = g_h[((size_t)b*Qc + t0 + t)*Hc + h];
  }
  for(int e=tid; e<34*Hc; e+=256){
    int j = e/Hc, h = e%Hc;
    Ws[j][h] = (j<2) ? rpw[j*Hc + h] : gw[(j-2)*Hc + h];
  }
  if(tid<34) bs[tid] = (tid<2) ? rpb[tid] : gb[tid-2];
  __syncthreads();
  {
    int w = tid>>5, lane = tid&31;
    for(int rep=0; rep<2; rep++){
      int t = w + rep*8;
      float v[6]; float s = 0.f;
#pragma unroll
      for(int j=0;j<6;j++){ v[j] = Hs[t][lane+32*j]; s += v[j]; }
      s = wred(s);
      float m = s*(1.f/192.f);
      float sq = 0.f;
#pragma unroll
      for(int j=0;j<6;j++){ float d = v[j]-m; sq += d*d; }
      sq = wred(sq);
      float rstd = rsqrtf(sq*(1.f/192.f) + 1e-5f);
#pragma unroll
      for(int j=0;j<6;j++){
        int c = lane+32*j;
        Hs[t][c] = (v[j]-m)*rstd*olnw[c] + olnb[c];
      }
    }
  }
  __syncthreads();
  if(t0 == Qc-16){
    for(int e=tid; e<Hc; e+=256)
      g_hseq[((size_t)b*Qc + (Qc-1))*Hc + e] = Hs[15][e];
  }
  for(int e=tid; e<16*34; e+=256){
    int t = e/34, j = e%34;
    float acc = bs[j];
    for(int h=0;h<Hc;h++) acc += Hs[t][h]*Ws[j][h];
    float v;
    if(j==0)      v = 1.25f*sigm(acc);
    else if(j==1) v = PI_F*tanhf(acc);
    else          v = sigm(acc);
    outs[t][j] = v;
  }
  __syncthreads();
  if(tid<16){
    float rho = outs[tid][0], phi = outs[tid][1];
    float sn, cs; sincosf(phi, &sn, &cs);
    outs[tid][0] = rho*cs;
    outs[tid][1] = rho*sn;
  }
  __syncthreads();
  for(int e=tid; e<16*34; e+=256){
    int t = e/34, j = e%34;
    g_rpg[((size_t)b*Qc + t0 + t)*34 + j] = outs[t][j];
  }
}

// ============ 8) sequential Kalman scan + fused rollout init ============
__global__ void k_scan(const float* __restrict__ x){
  int b = blockIdx.x, d = threadIdx.x;
  const float* xb = x + (size_t)b*Qc*Dc;
  const float* rp = g_rpg + (size_t)b*Qc*34;
  float xp = xb[d];
  float sign = (d<16) ? -1.f : 1.f;
  float rc = rp[0], rs = rp[1], gn = rp[2+d], y = xb[d];
  for(int t=0;t<Qc;t++){
    float nrc=0.f, nrs=0.f, ngn=0.f, ny=0.f;
    if(t+1<Qc){
      const float* r = rp + (size_t)(t+1)*34;
      nrc = r[0]; nrs = r[1]; ngn = r[2+d];
      ny = xb[(size_t)(t+1)*Dc + d];
    }
    float other = __shfl_xor_sync(0xffffffffu, xp, 16);
    float xpri = rc*xp + sign*rs*other;
    xp = xpri + gn*(y - xpri);
    rc=nrc; rs=nrs; gn=ngn; y=ny;
  }
  g_curr[b*Dc + d] = xp;
  for(int h=d; h<Hc; h+=32)
    g_hr[b*Hc + h] = g_hseq[((size_t)b*Qc + (Qc-1))*Hc + h];
  if(b==0 && d==0){ g_cnt = 0u; g_gen = 0u; }
}

__device__ __forceinline__ void gridbar(unsigned NB){
  __threadfence();
  __syncthreads();
  if(threadIdx.x==0){
    unsigned gen = g_gen;
    if(atomicAdd(&g_cnt, 1u) == NB-1u){
      g_cnt = 0u;
      __threadfence();
      g_gen = gen + 1u;
    } else {
      while(g_gen == gen) __nanosleep(64);
    }
    __threadfence();
  }
  __syncthreads();
}

// ============ 10) persistent rollout ============
__global__ void __launch_bounds__(256) k_roll(const float* __restrict__ riW,
                                              const float* __restrict__ riB,
                                              const float* __restrict__ whh,
                                              const float* __restrict__ bhh,
                                              const float* __restrict__ wih,
                                              const float* __restrict__ bih,
                                              const float* __restrict__ lnw,
                                              const float* __restrict__ lnb,
                                              const float* __restrict__ rpw,
                                              const float* __restrict__ rpb,
                                              float* __restrict__ dout){
  __shared__ float In[32][33];
  __shared__ __align__(16) float Wt[32][68];
  __shared__ float red[12];
  __shared__ float curs[Dc];
  int tid = threadIdx.x;
  unsigned NB = gridDim.x;
  for(int step=0; step<WOUTc; step++){
    {
      int u = blockIdx.x;
      if(u < 96){
        int ox = u%12, by = u/12;
        bool xpath = ox<3;
        int o0 = xpath? ox*64 : (ox-3)*64;
        int b0 = by*32;
        int K  = xpath? (Hc+Dc) : Hc;
        const float* W = xpath? riW : whh;
        int tb = tid&15, to = tid>>4;
        float acc[2][4] = {};
        int nch = K/32;
        for(int ch=0; ch<nch; ch++){
          int c0 = ch*32;
          __syncthreads();
          for(int e=tid; e<1024; e+=256){
            int bb = e>>5, k = e&31;
            float v;
            if(xpath && ch==6) v = __ldcg(&g_curr[(b0+bb)*Dc + k]);
            else               v = __ldcg(&g_hr[(b0+bb)*Hc + c0 + k]);
            In[k][bb] = v;
          }
          for(int e=tid; e<2048; e+=256){
            int o = e>>5, k = e&31;
            Wt[k][o] = W[(size_t)(o0+o)*K + c0 + k];
          }
          __syncthreads();
#pragma unroll
          for(int k=0;k<32;k++){
            float a0 = In[k][tb*2], a1 = In[k][tb*2+1];
            float4 w = *(const float4*)&Wt[k][to<<2];
            acc[0][0]+=a0*w.x; acc[0][1]+=a0*w.y; acc[0][2]+=a0*w.z; acc[0][3]+=a0*w.w;
            acc[1][0]+=a1*w.x; acc[1][1]+=a1*w.y; acc[1][2]+=a1*w.z; acc[1][3]+=a1*w.w;
          }
        }
#pragma unroll
        for(int i=0;i<2;i++){
          int b = b0 + tb*2 + i;
#pragma unroll
          for(int j=0;j<4;j++){
            int o = o0 + (to<<2) + j;
            float v = acc[i][j];
            if(xpath) __stcg(&g_xr[b*Hc + o], tanhf(v + riB[o]));
            else      __stcg(&g_gh[b*3*Hc + o], v + bhh[o]);
          }
        }
      }
    }
    gridbar(NB);
    {
      int u = blockIdx.x;
      if(u < 72){
        int o0 = (u%9)*64, b0 = (u/9)*32;
        int tb = tid&15, to = tid>>4;
        float acc[2][4] = {};
        for(int ch=0; ch<6; ch++){
          int c0 = ch*32;
          __syncthreads();
          for(int e=tid; e<1024; e+=256){
            int bb = e>>5, k = e&31;
            In[k][bb] = __ldcg(&g_xr[(b0+bb)*Hc + c0 + k]);
          }
          for(int e=tid; e<2048; e+=256){
            int o = e>>5, k = e&31;
            Wt[k][o] = wih[(size_t)(o0+o)*Hc + c0 + k];
          }
          __syncthreads();
#pragma unroll
          for(int k=0;k<32;k++){
            float a0 = In[k][tb*2], a1 = In[k][tb*2+1];
            float4 w = *(const float4*)&Wt[k][to<<2];
            acc[0][0]+=a0*w.x; acc[0][1]+=a0*w.y; acc[0][2]+=a0*w.z; acc[0][3]+=a0*w.w;
            acc[1][0]+=a1*w.x; acc[1][1]+=a1*w.y; acc[1][2]+=a1*w.z; acc[1][3]+=a1*w.w;
          }
        }
#pragma unroll
        for(int i=0;i<2;i++){
          int b = b0 + tb*2 + i;
#pragma unroll
          for(int j=0;j<4;j++){
            int o = o0 + (to<<2) + j;
            __stcg(&g_gi[b*3*Hc + o], acc[i][j] + bih[o]);
          }
        }
      }
    }
    gridbar(NB);
    for(int rep=0; rep<2; rep++){
      int b = blockIdx.x + rep*128;
      int o = tid;
      bool act = o < Hc;
      int w = o>>5, lane = o&31;
      float v = 0.f, hr = 0.f;
      if(act){
        float gi0 = __ldcg(&g_gi[b*576 + o]),       gh0 = __ldcg(&g_gh[b*576 + o]);
        float gi1 = __ldcg(&g_gi[b*576 + 192 + o]), gh1 = __ldcg(&g_gh[b*576 + 192 + o]);
        float gi2 = __ldcg(&g_gi[b*576 + 384 + o]), gh2 = __ldcg(&g_gh[b*576 + 384 + o]);
        hr = __ldcg(&g_hr[b*Hc + o]);
        float r = sigm(gi0 + gh0);
        float z = sigm(gi1 + gh1);
        float n = tanhf(gi2 + r*gh2);
        v = (1.f - z)*n + z*hr;
      }
      if(o<Dc) curs[o] = __ldcg(&g_curr[b*Dc + o]);
      float s = wred(act? v : 0.f);
      if(lane==0 && w<6) red[w] = s;
      __syncthreads();
      float m = (red[0]+red[1]+red[2]+red[3]+red[4]+red[5])*(1.f/192.f);
      __syncthreads();
      float d0 = act? (v - m) : 0.f;
      s = wred(d0*d0);
      if(lane==0 && w<6) red[w] = s;
      __syncthreads();
      float var = (red[0]+red[1]+red[2]+red[3]+red[4]+red[5])*(1.f/192.f);
      float hn = 0.f;
      if(act){
        hn = d0*rsqrtf(var + 1e-5f)*lnw[o] + lnb[o];
        __stcg(&g_hr[b*Hc + o], hn);
      }
      __syncthreads();
      float s0 = wred(act? hn*rpw[o] : 0.f);
      float s1 = wred(act? hn*rpw[Hc + o] : 0.f);
      if(lane==0 && w<6){ red[w] = s0; red[6+w] = s1; }
      __syncthreads();
      float p0 = red[0]+red[1]+red[2]+red[3]+red[4]+red[5] + rpb[0];
      float p1 = red[6]+red[7]+red[8]+red[9]+red[10]+red[11] + rpb[1];
      float rho = 1.25f*sigm(p0);
      float phi = PI_F*tanhf(p1);
      float sn, cs; sincosf(phi, &sn, &cs);
      float rc = rho*cs, rs = rho*sn;
      if(o<Dc){
        float self = curs[o];
        float other = curs[o^16];
        float outv = rc*self + ((o<16)? -rs : rs)*other;
        __stcg(&g_curr[b*Dc + o], outv);
        dout[((size_t)b*WOUTc + step)*Dc + o] = outv;
      }
      __syncthreads();
    }
    gridbar(NB);
  }
}

// ============================== launch ==============================
extern "C" void kernel_launch(void* const* d_in, const int* in_sizes, int n_in,
                              void* d_out, int out_size){
  const float* x_in    = (const float*)d_in[0];
  const float* inp_w   = (const float*)d_in[1];
  const float* inp_b   = (const float*)d_in[2];
  const float* b_dw_w  = (const float*)d_in[3];
  const float* b_dw_b  = (const float*)d_in[4];
  const float* b_ln_w  = (const float*)d_in[5];
  const float* b_ln_b  = (const float*)d_in[6];
  const float* b_pw1_w = (const float*)d_in[7];
  const float* b_pw1_b = (const float*)d_in[8];
  const float* b_grn_g = (const float*)d_in[9];
  const float* b_grn_b = (const float*)d_in[10];
  const float* b_pw2_w = (const float*)d_in[11];
  const float* b_pw2_b = (const float*)d_in[12];
  const float* out_ln_w= (const float*)d_in[13];
  const float* out_ln_b= (const float*)d_in[14];
  const float* fc_rp_w = (const float*)d_in[15];
  const float* fc_rp_b = (const float*)d_in[16];
  const float* fc_gain_w=(const float*)d_in[17];
  const float* fc_gain_b=(const float*)d_in[18];
  const float* roll_in_w=(const float*)d_in[19];
  const float* roll_in_b=(const float*)d_in[20];
  const float* gru_wih = (const float*)d_in[21];
  const float* gru_whh = (const float*)d_in[22];
  const float* gru_bih = (const float*)d_in[23];
  const float* gru_bhh = (const float*)d_in[24];
  const float* roll_ln_w=(const float*)d_in[25];
  const float* roll_ln_b=(const float*)d_in[26];
  const float* fc_rp_r_w=(const float*)d_in[27];
  const float* fc_rp_r_b=(const float*)d_in[28];
  float* dout = (float*)d_out;

  k_featproj<<<dim3(Qc/64, Hc/64, Bc), 256>>>(x_in, inp_w, inp_b);

  for(int i=0;i<2;i++){
    k_dwconv_ln<<<dim3(Qc/16, Bc), 256>>>(b_dw_w + (size_t)i*Hc*KERc,
                                          b_dw_b + (size_t)i*Hc,
                                          b_ln_w + (size_t)i*Hc,
                                          b_ln_b + (size_t)i*Hc);
    k_pw1x<<<dim3(Qc/128, HIDc/64, Bc), 128>>>(b_pw1_w + (size_t)i*HIDc*Hc,
                                               b_pw1_b + (size_t)i*HIDc);
    k_pw2x<<<dim3(Qc/128, Hc/64, Bc), 128>>>(b_pw2_w + (size_t)i*Hc*HIDc,
                                             b_pw2_b + (size_t)i*Hc,
                                             b_grn_b + (size_t)i*HIDc,
                                             b_grn_g + (size_t)i*HIDc);
  }

  k_scanprep<<<dim3(Qc/16, Bc), 256>>>(out_ln_w, out_ln_b,
                                       fc_rp_w, fc_rp_b, fc_gain_w, fc_gain_b);
  k_scan<<<Bc, 32>>>(x_in);

  k_roll<<<128, 256>>>(roll_in_w, roll_in_b, gru_whh, gru_bhh,
                       gru_wih, gru_bih, roll_ln_w, roll_ln_b,
                       fc_rp_r_w, fc_rp_r_b, dout);
}

// round 17
// speedup vs baseline: 1.2643x; 1.1632x over previous
#include <cuda_runtime.h>
#include <cuda_bf16.h>
#include <math.h>
#include <stdint.h>

#define Bc 256
#define Qc 512
#define Dc 32
#define Hc 192
#define HIDc 384
#define INCHc 96
#define KERc 9
#define WOUTc 64
#define PI_F 3.14159265358979f

// ---------------- scratch (all fp32 — trunk precision is load-bearing) ----------------
__device__ __align__(16) float g_h   [(size_t)Bc*Qc*Hc];    // residual (B,Q,H)
__device__ __align__(16) float g_af  [(size_t)Bc*Qc*Hc];    // LN'd act (B,Q,H)
__device__ __align__(16) float g_midf[(size_t)Bc*Qc*HIDc];  // pw1 out  (B,Q,HID)
__device__ __align__(16) float g_hseq[(size_t)Bc*Qc*Hc];    // only t=511 rows used
__device__ float g_gxsq[Bc*HIDc];
__device__ float g_rpg [(size_t)Bc*Qc*34];
__device__ float g_hr  [Bc*Hc];
__device__ float g_xr  [Bc*Hc];
__device__ float g_gi  [Bc*3*Hc];
__device__ float g_gh  [Bc*3*Hc];
__device__ float g_curr[Bc*Dc];
__device__ unsigned g_cnt;
__device__ volatile unsigned g_gen;

// ---------------- helpers ----------------
__device__ __forceinline__ float sigm(float x){ return 1.f/(1.f+expf(-x)); }
__device__ __forceinline__ float gelu_exact(float x){ return 0.5f*x*(1.f+erff(x*0.70710678118654752f)); }
__device__ __forceinline__ float wred(float v){
#pragma unroll
  for(int s=16;s;s>>=1) v += __shfl_xor_sync(0xffffffffu, v, s);
  return v;
}
__device__ __forceinline__ unsigned long long dupf(float w){
  unsigned long long r;
  asm("mov.b64 %0, {%1, %1};" : "=l"(r) : "f"(w));
  return r;
}
__device__ __forceinline__ void ffma2(unsigned long long &acc, unsigned long long a, unsigned long long b){
  asm("fma.rn.f32x2 %0, %1, %2, %0;" : "+l"(acc) : "l"(a), "l"(b));
}
__device__ __forceinline__ float2 unpk(unsigned long long p){
  float2 f; asm("mov.b64 {%0, %1}, %2;" : "=f"(f.x), "=f"(f.y) : "l"(p));
  return f;
}

// ============ 1) features + input projection -> g_h (B,Q,H) ============
__global__ void __launch_bounds__(256) k_featproj(const float* __restrict__ x,
                                                  const float* __restrict__ W,
                                                  const float* __restrict__ bias){
  int t0 = blockIdx.x*64, o0 = blockIdx.y*64, b = blockIdx.z;
  __shared__ __align__(16) float Xs[66][33];
  __shared__ __align__(16) float As[32][64];
  __shared__ __align__(16) float Ws[32][68];
  int tid = threadIdx.x;
  for(int e=tid; e<66*32; e+=256){
    int i = e>>5, d = e&31;
    int tg = t0 - 2 + i;
    float v = 0.f;
    if(tg>=0 && tg<Qc) v = x[((size_t)b*Qc + tg)*Dc + d];
    Xs[i][d] = v;
  }
  int tx = tid & 15, ty = tid >> 4;
  float acc[4][4] = {};
  for(int j=0;j<3;j++){
    __syncthreads();
    for(int e=tid; e<2048; e+=256){
      int k = e>>6, t = e&63;
      int tg = t0+t;
      float x0 = Xs[t+2][k], x1 = Xs[t+1][k], x2 = Xs[t][k];
      float v;
      if(j==0)      v = x0;
      else if(j==1) v = (tg>=1)? x0-x1 : 0.f;
      else          v = (tg>=2)? (x0-2.f*x1+x2) : ((tg==1)? x0-x1 : 0.f);
      As[k][t] = v;
    }
    for(int e=tid; e<2048; e+=256){
      int o = e>>5, k = e&31;
      Ws[k][o] = W[(size_t)(o0+o)*INCHc + j*32 + k];
    }
    __syncthreads();
#pragma unroll
    for(int k=0;k<32;k++){
      float4 a = *(const float4*)&As[k][tx<<2];
      float4 w = *(const float4*)&Ws[k][ty<<2];
      acc[0][0]+=w.x*a.x; acc[0][1]+=w.x*a.y; acc[0][2]+=w.x*a.z; acc[0][3]+=w.x*a.w;
      acc[1][0]+=w.y*a.x; acc[1][1]+=w.y*a.y; acc[1][2]+=w.y*a.z; acc[1][3]+=w.y*a.w;
      acc[2][0]+=w.z*a.x; acc[2][1]+=w.z*a.y; acc[2][2]+=w.z*a.z; acc[2][3]+=w.z*a.w;
      acc[3][0]+=w.w*a.x; acc[3][1]+=w.w*a.y; acc[3][2]+=w.w*a.z; acc[3][3]+=w.w*a.w;
    }
  }
  float4 bo = *(const float4*)&bias[o0 + (ty<<2)];
#pragma unroll
  for(int jj=0;jj<4;jj++){
    int t = t0 + (tx<<2) + jj;
    float4 v;
    v.x = acc[0][jj] + bo.x;
    v.y = acc[1][jj] + bo.y;
    v.z = acc[2][jj] + bo.z;
    v.w = acc[3][jj] + bo.w;
    *(float4*)&g_h[((size_t)b*Qc + t)*Hc + o0 + (ty<<2)] = v;
  }
}

// ============ 2) dwconv (k=9 edge pad) + LN -> g_af fp32 (B,Q,H); zero gxsq ============
__global__ void __launch_bounds__(256) k_dwconv_ln(const float* __restrict__ dww,
                                                   const float* __restrict__ dwb,
                                                   const float* __restrict__ lnw,
                                                   const float* __restrict__ lnb){
  int t0 = blockIdx.x*16, b = blockIdx.y;
  __shared__ __align__(16) float In[24][Hc];
  __shared__ __align__(16) float Outp[16][Hc];
  __shared__ float Wd[Hc*KERc];
  __shared__ float Bd[Hc], Lw[Hc], Lb[Hc];
  int tid = threadIdx.x;
  if(blockIdx.x==0){
    for(int e=tid; e<HIDc; e+=256) g_gxsq[b*HIDc+e] = 0.f;
  }
  for(int e=tid; e<24*48; e+=256){
    int i = e/48, q = e%48;
    int tg = t0 - 4 + i;
    tg = tg < 0 ? 0 : (tg > Qc-1 ? Qc-1 : tg);
    *(float4*)&In[i][q*4] = *(const float4*)&g_h[((size_t)b*Qc + tg)*Hc + q*4];
  }
  for(int e=tid; e<Hc*KERc; e+=256) Wd[e] = dww[e];
  for(int e=tid; e<Hc; e+=256){ Bd[e] = dwb[e]; Lw[e] = lnw[e]; Lb[e] = lnb[e]; }
  __syncthreads();
  for(int e=tid; e<16*Hc; e+=256){
    int t = e/Hc, c = e%Hc;
    float acc = Bd[c];
#pragma unroll
    for(int k=0;k<KERc;k++) acc += In[t+k][c]*Wd[c*KERc+k];
    Outp[t][c] = acc;
  }
  __syncthreads();
  int w = tid>>5, lane = tid&31;
  for(int rep=0; rep<2; rep++){
    int t = w + rep*8;
    float v[6]; float s = 0.f;
#pragma unroll
    for(int j=0;j<6;j++){ v[j] = Outp[t][lane+32*j]; s += v[j]; }
    s = wred(s);
    float m = s*(1.f/192.f);
    float sq = 0.f;
#pragma unroll
    for(int j=0;j<6;j++){ float d = v[j]-m; sq += d*d; }
    sq = wred(sq);
    float rstd = rsqrtf(sq*(1.f/192.f) + 1e-5f);
#pragma unroll
    for(int j=0;j<6;j++){
      int c = lane+32*j;
      Outp[t][c] = (v[j]-m)*rstd*Lw[c] + Lb[c];
    }
  }
  __syncthreads();
  for(int e=tid; e<16*48; e+=256){
    int t = e/48, q = e%48;
    *(float4*)&g_af[((size_t)b*Qc + t0 + t)*Hc + q*4] = *(float4*)&Outp[t][q*4];
  }
}

// ============ 3) pw1: f32x2 GEMM (128t x 64o, K=192), t-pairs packed; + bias + GELU + fused gx ============
__global__ void __launch_bounds__(128,4) k_pw1x(const float* __restrict__ W,
                                                const float* __restrict__ bias){
  __shared__ __align__(16) float As[32][132];
  __shared__ __align__(16) float Ws[32][68];
  __shared__ float osq[64];
  int t0 = blockIdx.x*128, o0 = blockIdx.y*64, b = blockIdx.z;
  int tid = threadIdx.x, tx = tid&15, ty = tid>>4;  // ty 0..7
  if(tid<64) osq[tid] = 0.f;
  unsigned long long acc[4][8] = {};   // [o][t-pair: 0..3 grp0, 4..7 grp1]
  const float* Ag = g_af + ((size_t)b*Qc + t0)*Hc;
  for(int c0=0;c0<Hc;c0+=32){
    __syncthreads();
    for(int e=tid;e<1024;e+=128){
      int kq=e&7, t=e>>3;
      float4 v = *(const float4*)&Ag[(size_t)t*Hc + c0 + kq*4];
      As[kq*4+0][t]=v.x; As[kq*4+1][t]=v.y; As[kq*4+2][t]=v.z; As[kq*4+3][t]=v.w;
    }
    for(int e=tid;e<512;e+=128){
      int o=e>>3, kq=e&7;
      float4 w = *(const float4*)&W[(size_t)(o0+o)*Hc + c0 + kq*4];
      Ws[kq*4+0][o]=w.x; Ws[kq*4+1][o]=w.y; Ws[kq*4+2][o]=w.z; Ws[kq*4+3][o]=w.w;
    }
    __syncthreads();
#pragma unroll 8
    for(int k=0;k<32;k++){
      ulonglong2 a01 = *(const ulonglong2*)&As[k][ty*8];
      ulonglong2 a23 = *(const ulonglong2*)&As[k][ty*8+4];
      ulonglong2 b01 = *(const ulonglong2*)&As[k][64+ty*8];
      ulonglong2 b23 = *(const ulonglong2*)&As[k][64+ty*8+4];
      float4 w = *(const float4*)&Ws[k][tx*4];
      unsigned long long w0=dupf(w.x), w1=dupf(w.y), w2=dupf(w.z), w3=dupf(w.w);
      ffma2(acc[0][0], w0, a01.x); ffma2(acc[0][1], w0, a01.y);
      ffma2(acc[0][2], w0, a23.x); ffma2(acc[0][3], w0, a23.y);
      ffma2(acc[0][4], w0, b01.x); ffma2(acc[0][5], w0, b01.y);
      ffma2(acc[0][6], w0, b23.x); ffma2(acc[0][7], w0, b23.y);
      ffma2(acc[1][0], w1, a01.x); ffma2(acc[1][1], w1, a01.y);
      ffma2(acc[1][2], w1, a23.x); ffma2(acc[1][3], w1, a23.y);
      ffma2(acc[1][4], w1, b01.x); ffma2(acc[1][5], w1, b01.y);
      ffma2(acc[1][6], w1, b23.x); ffma2(acc[1][7], w1, b23.y);
      ffma2(acc[2][0], w2, a01.x); ffma2(acc[2][1], w2, a01.y);
      ffma2(acc[2][2], w2, a23.x); ffma2(acc[2][3], w2, a23.y);
      ffma2(acc[2][4], w2, b01.x); ffma2(acc[2][5], w2, b01.y);
      ffma2(acc[2][6], w2, b23.x); ffma2(acc[2][7], w2, b23.y);
      ffma2(acc[3][0], w3, a01.x); ffma2(acc[3][1], w3, a01.y);
      ffma2(acc[3][2], w3, a23.x); ffma2(acc[3][3], w3, a23.y);
      ffma2(acc[3][4], w3, b01.x); ffma2(acc[3][5], w3, b01.y);
      ffma2(acc[3][6], w3, b23.x); ffma2(acc[3][7], w3, b23.y);
    }
  }
  float4 bo = *(const float4*)&bias[o0 + tx*4];
  float sq[4] = {};
#pragma unroll
  for(int g=0;g<2;g++){
#pragma unroll
    for(int j=0;j<8;j++){
      int t = t0 + g*64 + ty*8 + j;
      int tp = g*4 + (j>>1);
      float2 p0 = unpk(acc[0][tp]);
      float2 p1 = unpk(acc[1][tp]);
      float2 p2 = unpk(acc[2][tp]);
      float2 p3 = unpk(acc[3][tp]);
      float4 v;
      v.x = gelu_exact(((j&1)? p0.y : p0.x) + bo.x);
      v.y = gelu_exact(((j&1)? p1.y : p1.x) + bo.y);
      v.z = gelu_exact(((j&1)? p2.y : p2.x) + bo.z);
      v.w = gelu_exact(((j&1)? p3.y : p3.x) + bo.w);
      sq[0]+=v.x*v.x; sq[1]+=v.y*v.y; sq[2]+=v.z*v.z; sq[3]+=v.w*v.w;
      *(float4*)&g_midf[((size_t)b*Qc + t)*HIDc + o0 + tx*4] = v;
    }
  }
  atomicAdd(&osq[tx*4+0], sq[0]);
  atomicAdd(&osq[tx*4+1], sq[1]);
  atomicAdd(&osq[tx*4+2], sq[2]);
  atomicAdd(&osq[tx*4+3], sq[3]);
  __syncthreads();
  if(tid<64) atomicAdd(&g_gxsq[b*HIDc + o0 + tid], osq[tid]);
}

// ============ 5) pw2: f32x2 GEMM (128t x 64o, K=384), t-pairs packed; GRN in-CTA + residual ============
__global__ void __launch_bounds__(128,4) k_pw2x(const float* __restrict__ W,
                                                const float* __restrict__ bias,
                                                const float* __restrict__ grnb,
                                                const float* __restrict__ gg){
  __shared__ __align__(16) float As[32][132];
  __shared__ __align__(16) float Ws[32][68];
  __shared__ float sc_s[HIDc], gb_s[HIDc];
  __shared__ float sred[4];
  int t0 = blockIdx.x*128, o0 = blockIdx.y*64, b = blockIdx.z;
  int tid = threadIdx.x, tx = tid&15, ty = tid>>4;
  // ---- fused GRN scale (redundant per CTA, deterministic) ----
  {
    int wid = tid>>5, lane = tid&31;
    float v3[3]; float psum = 0.f;
#pragma unroll
    for(int i=0;i<3;i++){
      float vv = sqrtf(g_gxsq[b*HIDc + tid*3 + i]);
      v3[i] = vv; psum += vv;
    }
    psum = wred(psum);
    if(lane==0) sred[wid] = psum;
    __syncthreads();
    float mean = (sred[0]+sred[1]+sred[2]+sred[3])*(1.f/384.f);
#pragma unroll
    for(int i=0;i<3;i++){
      int o = tid*3 + i;
      sc_s[o] = 1.f + gg[o]*v3[i]/(mean + 1e-6f);
      gb_s[o] = grnb[o];
    }
  }
  unsigned long long acc[4][8] = {};
  const float* Ag = g_midf + ((size_t)b*Qc + t0)*HIDc;
  for(int c0=0;c0<HIDc;c0+=32){
    __syncthreads();
    for(int e=tid;e<1024;e+=128){
      int kq=e&7, t=e>>3;
      int c = c0 + kq*4;
      float4 m = *(const float4*)&Ag[(size_t)t*HIDc + c];
      As[kq*4+0][t] = m.x*sc_s[c+0] + gb_s[c+0];
      As[kq*4+1][t] = m.y*sc_s[c+1] + gb_s[c+1];
      As[kq*4+2][t] = m.z*sc_s[c+2] + gb_s[c+2];
      As[kq*4+3][t] = m.w*sc_s[c+3] + gb_s[c+3];
    }
    for(int e=tid;e<512;e+=128){
      int o=e>>3, kq=e&7;
      float4 w = *(const float4*)&W[(size_t)(o0+o)*HIDc + c0 + kq*4];
      Ws[kq*4+0][o]=w.x; Ws[kq*4+1][o]=w.y; Ws[kq*4+2][o]=w.z; Ws[kq*4+3][o]=w.w;
    }
    __syncthreads();
#pragma unroll 8
    for(int k=0;k<32;k++){
      ulonglong2 a01 = *(const ulonglong2*)&As[k][ty*8];
      ulonglong2 a23 = *(const ulonglong2*)&As[k][ty*8+4];
      ulonglong2 b01 = *(const ulonglong2*)&As[k][64+ty*8];
      ulonglong2 b23 = *(const ulonglong2*)&As[k][64+ty*8+4];
      float4 w = *(const float4*)&Ws[k][tx*4];
      unsigned long long w0=dupf(w.x), w1=dupf(w.y), w2=dupf(w.z), w3=dupf(w.w);
      ffma2(acc[0][0], w0, a01.x); ffma2(acc[0][1], w0, a01.y);
      ffma2(acc[0][2], w0, a23.x); ffma2(acc[0][3], w0, a23.y);
      ffma2(acc[0][4], w0, b01.x); ffma2(acc[0][5], w0, b01.y);
      ffma2(acc[0][6], w0, b23.x); ffma2(acc[0][7], w0, b23.y);
      ffma2(acc[1][0], w1, a01.x); ffma2(acc[1][1], w1, a01.y);
      ffma2(acc[1][2], w1, a23.x); ffma2(acc[1][3], w1, a23.y);
      ffma2(acc[1][4], w1, b01.x); ffma2(acc[1][5], w1, b01.y);
      ffma2(acc[1][6], w1, b23.x); ffma2(acc[1][7], w1, b23.y);
      ffma2(acc[2][0], w2, a01.x); ffma2(acc[2][1], w2, a01.y);
      ffma2(acc[2][2], w2, a23.x); ffma2(acc[2][3], w2, a23.y);
      ffma2(acc[2][4], w2, b01.x); ffma2(acc[2][5], w2, b01.y);
      ffma2(acc[2][6], w2, b23.x); ffma2(acc[2][7], w2, b23.y);
      ffma2(acc[3][0], w3, a01.x); ffma2(acc[3][1], w3, a01.y);
      ffma2(acc[3][2], w3, a23.x); ffma2(acc[3][3], w3, a23.y);
      ffma2(acc[3][4], w3, b01.x); ffma2(acc[3][5], w3, b01.y);
      ffma2(acc[3][6], w3, b23.x); ffma2(acc[3][7], w3, b23.y);
    }
  }
  float4 bo = *(const float4*)&bias[o0 + tx*4];
#pragma unroll
  for(int g=0;g<2;g++){
#pragma unroll
    for(int j=0;j<8;j++){
      int t = t0 + g*64 + ty*8 + j;
      int tp = g*4 + (j>>1);
      float* hrow = g_h + ((size_t)b*Qc + t)*Hc + o0 + tx*4;
      float4 h = *(float4*)hrow;
      float2 p0 = unpk(acc[0][tp]);
      float2 p1 = unpk(acc[1][tp]);
      float2 p2 = unpk(acc[2][tp]);
      float2 p3 = unpk(acc[3][tp]);
      h.x += ((j&1)? p0.y : p0.x) + bo.x;
      h.y += ((j&1)? p1.y : p1.x) + bo.y;
      h.z += ((j&1)? p2.y : p2.x) + bo.z;
      h.w += ((j&1)? p3.y : p3.x) + bo.w;
      *(float4*)hrow = h;
    }
  }
}

// ============ 7) Kalman precompute with fused output-LN ============
__global__ void __launch_bounds__(256) k_scanprep(const float* __restrict__ olnw,
                                                  const float* __restrict__ olnb,
                                                  const float* __restrict__ rpw,
                                                  const float* __restrict__ rpb,
                                                  const float* __restrict__ gw,
                                                  const float* __restrict__ gb){
  int t0 = blockIdx.x*16, b = blockIdx.y;
  __shared__ float Hs[16][193];
  __shared__ float Ws[34][193];
  __shared__ float bs[34];
  __shared__ float outs[16][34];
  int tid = threadIdx.x;
  for(int e=tid; e<16*Hc; e+=256){
    int t = e/Hc, h = e%Hc;
    Hs[t][h] = g_h[((size_t)b*Qc + t0 + t)*Hc + h];
  }
  for(int e=tid; e<34*Hc; e+=256){
    int j = e/Hc, h = e%Hc;
    Ws[j][h] = (j<2) ? rpw[j*Hc + h] : gw[(j-2)*Hc + h];
  }
  if(tid<34) bs[tid] = (tid<2) ? rpb[tid] : gb[tid-2];
  __syncthreads();
  {
    int w = tid>>5, lane = tid&31;
    for(int rep=0; rep<2; rep++){
      int t = w + rep*8;
      float v[6]; float s = 0.f;
#pragma unroll
      for(int j=0;j<6;j++){ v[j] = Hs[t][lane+32*j]; s += v[j]; }
      s = wred(s);
      float m = s*(1.f/192.f);
      float sq = 0.f;
#pragma unroll
      for(int j=0;j<6;j++){ float d = v[j]-m; sq += d*d; }
      sq = wred(sq);
      float rstd = rsqrtf(sq*(1.f/192.f) + 1e-5f);
#pragma unroll
      for(int j=0;j<6;j++){
        int c = lane+32*j;
        Hs[t][c] = (v[j]-m)*rstd*olnw[c] + olnb[c];
      }
    }
  }
  __syncthreads();
  if(t0 == Qc-16){
    for(int e=tid; e<Hc; e+=256)
      g_hseq[((size_t)b*Qc + (Qc-1))*Hc + e] = Hs[15][e];
  }
  for(int e=tid; e<16*34; e+=256){
    int t = e/34, j = e%34;
    float acc = bs[j];
    for(int h=0;h<Hc;h++) acc += Hs[t][h]*Ws[j][h];
    float v;
    if(j==0)      v = 1.25f*sigm(acc);
    else if(j==1) v = PI_F*tanhf(acc);
    else          v = sigm(acc);
    outs[t][j] = v;
  }
  __syncthreads();
  if(tid<16){
    float rho = outs[tid][0], phi = outs[tid][1];
    float sn, cs; sincosf(phi, &sn, &cs);
    outs[tid][0] = rho*cs;
    outs[tid][1] = rho*sn;
  }
  __syncthreads();
  for(int e=tid; e<16*34; e+=256){
    int t = e/34, j = e%34;
    g_rpg[((size_t)b*Qc + t0 + t)*34 + j] = outs[t][j];
  }
}

// ============ 8) sequential Kalman scan + fused rollout init ============
__global__ void k_scan(const float* __restrict__ x){
  int b = blockIdx.x, d = threadIdx.x;
  const float* xb = x + (size_t)b*Qc*Dc;
  const float* rp = g_rpg + (size_t)b*Qc*34;
  float xp = xb[d];
  float sign = (d<16) ? -1.f : 1.f;
  float rc = rp[0], rs = rp[1], gn = rp[2+d], y = xb[d];
  for(int t=0;t<Qc;t++){
    float nrc=0.f, nrs=0.f, ngn=0.f, ny=0.f;
    if(t+1<Qc){
      const float* r = rp + (size_t)(t+1)*34;
      nrc = r[0]; nrs = r[1]; ngn = r[2+d];
      ny = xb[(size_t)(t+1)*Dc + d];
    }
    float other = __shfl_xor_sync(0xffffffffu, xp, 16);
    float xpri = rc*xp + sign*rs*other;
    xp = xpri + gn*(y - xpri);
    rc=nrc; rs=nrs; gn=ngn; y=ny;
  }
  g_curr[b*Dc + d] = xp;
  for(int h=d; h<Hc; h+=32)
    g_hr[b*Hc + h] = g_hseq[((size_t)b*Qc + (Qc-1))*Hc + h];
  if(b==0 && d==0){ g_cnt = 0u; g_gen = 0u; }
}

__device__ __forceinline__ void gridbar(unsigned NB){
  __threadfence();
  __syncthreads();
  if(threadIdx.x==0){
    unsigned gen = g_gen;
    if(atomicAdd(&g_cnt, 1u) == NB-1u){
      g_cnt = 0u;
      __threadfence();
      g_gen = gen + 1u;
    } else {
      while(g_gen == gen) __nanosleep(64);
    }
    __threadfence();
  }
  __syncthreads();
}

// ============ 10) persistent rollout: weight slices resident in dynamic smem ============
// dyn smem layout (floats): WA[224][68] @0, WB[192][68] @15232, IN[224][33] @28288
#define RW_WA 0
#define RW_WB 15232
#define RW_IN 28288
#define ROLL_SMEM ((15232 + 13056 + 7392)*4)
__global__ void __launch_bounds__(256) k_roll(const float* __restrict__ riW,
                                              const float* __restrict__ riB,
                                              const float* __restrict__ whh,
                                              const float* __restrict__ bhh,
                                              const float* __restrict__ wih,
                                              const float* __restrict__ bih,
                                              const float* __restrict__ lnw,
                                              const float* __restrict__ lnb,
                                              const float* __restrict__ rpw,
                                              const float* __restrict__ rpb,
                                              float* __restrict__ dout){
  extern __shared__ float dsm[];
  __shared__ float red[12];
  __shared__ float curs[Dc];
  int tid = threadIdx.x;
  unsigned NB = gridDim.x;    // 96
  int u = blockIdx.x;
  int ox = u % 12;
  bool xpath = ox < 3;
  int o0A = xpath ? ox*64 : (ox-3)*64;
  int b0 = (u/12)*32;
  int Ka = xpath ? (Hc+Dc) : Hc;
  const float* WmA = xpath ? riW : whh;
  int o0B = (u%9)*64, b0B = (u/9)*32;   // stage-B slice (u<72)
  int tb = tid&15, to = tid>>4;
  int w = tid>>5, lane = tid&31;

  // ---- one-time weight slice preload ----
  for(int e=tid; e<64*Ka; e+=256){
    int o = e / Ka, k = e % Ka;
    dsm[RW_WA + k*68 + o] = WmA[(size_t)(o0A+o)*Ka + k];
  }
  if(u < 72){
    for(int e=tid; e<64*Hc; e+=256){
      int o = e / Hc, k = e % Hc;
      dsm[RW_WB + k*68 + o] = wih[(size_t)(o0B+o)*Hc + k];
    }
  }
  __syncthreads();

  for(int step=0; step<WOUTc; step++){
    // ---- stage A: x = tanh(roll_in*[hr;curr]+b) or gh = whh*hr + bhh ----
    {
      for(int e=tid; e<32*Ka; e+=256){
        int bb = e / Ka, k = e % Ka;
        float v;
        if(xpath && k>=Hc) v = __ldcg(&g_curr[(b0+bb)*Dc + (k-Hc)]);
        else               v = __ldcg(&g_hr[(b0+bb)*Hc + k]);
        dsm[RW_IN + k*33 + bb] = v;
      }
      __syncthreads();
      float acc[2][4] = {};
      for(int k=0;k<Ka;k++){
        float a0 = dsm[RW_IN + k*33 + tb*2], a1 = dsm[RW_IN + k*33 + tb*2+1];
        float4 wv = *(const float4*)&dsm[RW_WA + k*68 + (to<<2)];
        acc[0][0]+=a0*wv.x; acc[0][1]+=a0*wv.y; acc[0][2]+=a0*wv.z; acc[0][3]+=a0*wv.w;
        acc[1][0]+=a1*wv.x; acc[1][1]+=a1*wv.y; acc[1][2]+=a1*wv.z; acc[1][3]+=a1*wv.w;
      }
#pragma unroll
      for(int i=0;i<2;i++){
        int b = b0 + tb*2 + i;
#pragma unroll
        for(int j=0;j<4;j++){
          int o = o0A + (to<<2) + j;
          float v = acc[i][j];
          if(xpath) __stcg(&g_xr[b*Hc + o], tanhf(v + riB[o]));
          else      __stcg(&g_gh[b*3*Hc + o], v + bhh[o]);
        }
      }
    }
    gridbar(NB);
    // ---- stage B: gi = wih*x + bih ----
    if(u < 72){
      for(int e=tid; e<32*Hc; e+=256){
        int bb = e / Hc, k = e % Hc;
        dsm[RW_IN + k*33 + bb] = __ldcg(&g_xr[(b0B+bb)*Hc + k]);
      }
      __syncthreads();
      float acc[2][4] = {};
      for(int k=0;k<Hc;k++){
        float a0 = dsm[RW_IN + k*33 + tb*2], a1 = dsm[RW_IN + k*33 + tb*2+1];
        float4 wv = *(const float4*)&dsm[RW_WB + k*68 + (to<<2)];
        acc[0][0]+=a0*wv.x; acc[0][1]+=a0*wv.y; acc[0][2]+=a0*wv.z; acc[0][3]+=a0*wv.w;
        acc[1][0]+=a1*wv.x; acc[1][1]+=a1*wv.y; acc[1][2]+=a1*wv.z; acc[1][3]+=a1*wv.w;
      }
#pragma unroll
      for(int i=0;i<2;i++){
        int b = b0B + tb*2 + i;
#pragma unroll
        for(int j=0;j<4;j++){
          int o = o0B + (to<<2) + j;
          __stcg(&g_gi[b*3*Hc + o], acc[i][j] + bih[o]);
        }
      }
    }
    gridbar(NB);
    // ---- stage C: gates + LN + rho/phi + rotate + store ----
    for(int b=u; b<Bc; b+=96){
      int o = tid;
      bool act = o < Hc;
      float v = 0.f, hr = 0.f;
      if(act){
        float gi0 = __ldcg(&g_gi[b*576 + o]),       gh0 = __ldcg(&g_gh[b*576 + o]);
        float gi1 = __ldcg(&g_gi[b*576 + 192 + o]), gh1 = __ldcg(&g_gh[b*576 + 192 + o]);
        float gi2 = __ldcg(&g_gi[b*576 + 384 + o]), gh2 = __ldcg(&g_gh[b*576 + 384 + o]);
        hr = __ldcg(&g_hr[b*Hc + o]);
        float r = sigm(gi0 + gh0);
        float z = sigm(gi1 + gh1);
        float n = tanhf(gi2 + r*gh2);
        v = (1.f - z)*n + z*hr;
      }
      if(o<Dc) curs[o] = __ldcg(&g_curr[b*Dc + o]);
      float s = wred(act? v : 0.f);
      if(lane==0 && w<6) red[w] = s;
      __syncthreads();
      float m = (red[0]+red[1]+red[2]+red[3]+red[4]+red[5])*(1.f/192.f);
      __syncthreads();
      float d0 = act? (v - m) : 0.f;
      s = wred(d0*d0);
      if(lane==0 && w<6) red[w] = s;
      __syncthreads();
      float var = (red[0]+red[1]+red[2]+red[3]+red[4]+red[5])*(1.f/192.f);
      float hn = 0.f;
      if(act){
        hn = d0*rsqrtf(var + 1e-5f)*lnw[o] + lnb[o];
        __stcg(&g_hr[b*Hc + o], hn);
      }
      __syncthreads();
      float s0 = wred(act? hn*rpw[o] : 0.f);
      float s1 = wred(act? hn*rpw[Hc + o] : 0.f);
      if(lane==0 && w<6){ red[w] = s0; red[6+w] = s1; }
      __syncthreads();
      float p0 = red[0]+red[1]+red[2]+red[3]+red[4]+red[5] + rpb[0];
      float p1 = red[6]+red[7]+red[8]+red[9]+red[10]+red[11] + rpb[1];
      float rho = 1.25f*sigm(p0);
      float phi = PI_F*tanhf(p1);
      float sn, cs; sincosf(phi, &sn, &cs);
      float rc = rho*cs, rs = rho*sn;
      if(o<Dc){
        float self = curs[o];
        float other = curs[o^16];
        float outv = rc*self + ((o<16)? -rs : rs)*other;
        __stcg(&g_curr[b*Dc + o], outv);
        dout[((size_t)b*WOUTc + step)*Dc + o] = outv;
      }
      __syncthreads();
    }
    gridbar(NB);
  }
}

// ============================== launch ==============================
extern "C" void kernel_launch(void* const* d_in, const int* in_sizes, int n_in,
                              void* d_out, int out_size){
  const float* x_in    = (const float*)d_in[0];
  const float* inp_w   = (const float*)d_in[1];
  const float* inp_b   = (const float*)d_in[2];
  const float* b_dw_w  = (const float*)d_in[3];
  const float* b_dw_b  = (const float*)d_in[4];
  const float* b_ln_w  = (const float*)d_in[5];
  const float* b_ln_b  = (const float*)d_in[6];
  const float* b_pw1_w = (const float*)d_in[7];
  const float* b_pw1_b = (const float*)d_in[8];
  const float* b_grn_g = (const float*)d_in[9];
  const float* b_grn_b = (const float*)d_in[10];
  const float* b_pw2_w = (const float*)d_in[11];
  const float* b_pw2_b = (const float*)d_in[12];
  const float* out_ln_w= (const float*)d_in[13];
  const float* out_ln_b= (const float*)d_in[14];
  const float* fc_rp_w = (const float*)d_in[15];
  const float* fc_rp_b = (const float*)d_in[16];
  const float* fc_gain_w=(const float*)d_in[17];
  const float* fc_gain_b=(const float*)d_in[18];
  const float* roll_in_w=(const float*)d_in[19];
  const float* roll_in_b=(const float*)d_in[20];
  const float* gru_wih = (const float*)d_in[21];
  const float* gru_whh = (const float*)d_in[22];
  const float* gru_bih = (const float*)d_in[23];
  const float* gru_bhh = (const float*)d_in[24];
  const float* roll_ln_w=(const float*)d_in[25];
  const float* roll_ln_b=(const float*)d_in[26];
  const float* fc_rp_r_w=(const float*)d_in[27];
  const float* fc_rp_r_b=(const float*)d_in[28];
  float* dout = (float*)d_out;

  cudaFuncSetAttribute(k_roll, cudaFuncAttributeMaxDynamicSharedMemorySize, ROLL_SMEM);

  k_featproj<<<dim3(Qc/64, Hc/64, Bc), 256>>>(x_in, inp_w, inp_b);

  for(int i=0;i<2;i++){
    k_dwconv_ln<<<dim3(Qc/16, Bc), 256>>>(b_dw_w + (size_t)i*Hc*KERc,
                                          b_dw_b + (size_t)i*Hc,
                                          b_ln_w + (size_t)i*Hc,
                                          b_ln_b + (size_t)i*Hc);
    k_pw1x<<<dim3(Qc/128, HIDc/64, Bc), 128>>>(b_pw1_w + (size_t)i*HIDc*Hc,
                                               b_pw1_b + (size_t)i*HIDc);
    k_pw2x<<<dim3(Qc/128, Hc/64, Bc), 128>>>(b_pw2_w + (size_t)i*Hc*HIDc,
                                             b_pw2_b + (size_t)i*Hc,
                                             b_grn_b + (size_t)i*HIDc,
                                             b_grn_g + (size_t)i*HIDc);
  }

  k_scanprep<<<dim3(Qc/16, Bc), 256>>>(out_ln_w, out_ln_b,
                                       fc_rp_w, fc_rp_b, fc_gain_w, fc_gain_b);
  k_scan<<<Bc, 32>>>(x_in);

  k_roll<<<96, 256, ROLL_SMEM>>>(roll_in_w, roll_in_b, gru_whh, gru_bhh,
                                 gru_wih, gru_bih, roll_ln_w, roll_ln_b,
                                 fc_rp_r_w, fc_rp_r_b, dout);
}